// round 1
// baseline (speedup 1.0000x reference)
#include <cuda_runtime.h>
#include <cuda_bf16.h>
#include <math_constants.h>

// Problem constants (fixed shapes for Attention_21801253995050)
#define Bsz 4
#define SEQ 2048
#define DMODEL 1024
#define NHEAD 16
#define HDIM 64
#define BH (Bsz * NHEAD)          // 64
#define MROWS (Bsz * SEQ)         // 8192
#define QKVN (3 * DMODEL)         // 3072

// Scratch (static device globals; no runtime allocation)
__device__ float g_qkv[MROWS * QKVN];                       // 25.2M floats
__device__ float g_scores[(size_t)BH * SEQ * SEQ];          // 268.4M floats (1 GiB)
__device__ float g_att[MROWS * DMODEL];                     // 8.4M floats

// ---------------------------------------------------------------------------
// Generic SGEMM with bias: C[M,N] = A[M,K] * B[K,N] + bias[N]
// BM=128, BN=128, BK=16, 256 threads, 8x8 register tile per thread.
// Requires M%128==0, N%128==0, K%16==0 (true for all our shapes).
// ---------------------------------------------------------------------------
#define BM 128
#define BN 128
#define BKT 16

__global__ __launch_bounds__(256) void sgemm_bias_kernel(
    const float* __restrict__ A, const float* __restrict__ B,
    const float* __restrict__ bias, float* __restrict__ C,
    int M, int N, int K)
{
    __shared__ float As[BKT][BM];
    __shared__ float Bs[BKT][BN];
    const int tid = threadIdx.x;
    const int trow = tid / 16;
    const int tcol = tid % 16;
    const int rowBase = blockIdx.y * BM;
    const int colBase = blockIdx.x * BN;

    float acc[8][8];
#pragma unroll
    for (int i = 0; i < 8; i++)
#pragma unroll
        for (int j = 0; j < 8; j++) acc[i][j] = 0.f;

    const float* Aptr = A + (size_t)rowBase * K;
    const float* Bptr = B + colBase;

    for (int k0 = 0; k0 < K; k0 += BKT) {
        // A tile: BM x BK, transposed into As
#pragma unroll
        for (int u = 0; u < 2; u++) {
            int unit = tid + u * 256;         // 0..511
            int r = unit >> 2;                // 0..127
            int cv = (unit & 3) * 4;          // 0,4,8,12
            float4 v = *reinterpret_cast<const float4*>(Aptr + (size_t)r * K + k0 + cv);
            As[cv + 0][r] = v.x; As[cv + 1][r] = v.y;
            As[cv + 2][r] = v.z; As[cv + 3][r] = v.w;
        }
        // B tile: BK x BN, direct
#pragma unroll
        for (int u = 0; u < 2; u++) {
            int unit = tid + u * 256;
            int r = unit >> 5;                // 0..15
            int c = (unit & 31) * 4;
            *reinterpret_cast<float4*>(&Bs[r][c]) =
                *reinterpret_cast<const float4*>(Bptr + (size_t)(k0 + r) * N + c);
        }
        __syncthreads();
#pragma unroll
        for (int k = 0; k < BKT; k++) {
            float a[8], b[8];
#pragma unroll
            for (int i = 0; i < 8; i++) a[i] = As[k][trow * 8 + i];
#pragma unroll
            for (int j = 0; j < 8; j++) b[j] = Bs[k][tcol * 8 + j];
#pragma unroll
            for (int i = 0; i < 8; i++)
#pragma unroll
                for (int j = 0; j < 8; j++)
                    acc[i][j] = fmaf(a[i], b[j], acc[i][j]);
        }
        __syncthreads();
    }

#pragma unroll
    for (int i = 0; i < 8; i++) {
        int r = rowBase + trow * 8 + i;
#pragma unroll
        for (int j = 0; j < 8; j += 4) {
            int c = colBase + tcol * 8 + j;
            float4 o;
            o.x = acc[i][j + 0] + bias[c + 0];
            o.y = acc[i][j + 1] + bias[c + 1];
            o.z = acc[i][j + 2] + bias[c + 2];
            o.w = acc[i][j + 3] + bias[c + 3];
            *reinterpret_cast<float4*>(C + (size_t)r * N + c) = o;
        }
    }
}

// ---------------------------------------------------------------------------
// Scores: per (b,h): S[i,j] = (Q_i . K_j) * 0.125, causal mask (j>i -> -1e4)
// grid: (S/BN, S/BM, BH). Fully-masked tiles write -1e4 without compute.
// ---------------------------------------------------------------------------
__global__ __launch_bounds__(256) void scores_kernel(
    const float* __restrict__ qkv, float* __restrict__ scores)
{
    const int bh = blockIdx.z;
    const int b = bh / NHEAD, h = bh % NHEAD;
    const int rowBase = blockIdx.y * BM;   // query i
    const int colBase = blockIdx.x * BN;   // key j
    float* Cb = scores + (size_t)bh * SEQ * SEQ;
    const int tid = threadIdx.x;

    if (colBase > rowBase + (BM - 1)) {
        // fully masked tile
        float4 mval = make_float4(-10000.f, -10000.f, -10000.f, -10000.f);
        for (int u = tid; u < BM * BN / 4; u += 256) {
            int r = u >> 5;
            int c = (u & 31) * 4;
            *reinterpret_cast<float4*>(Cb + (size_t)(rowBase + r) * SEQ + colBase + c) = mval;
        }
        return;
    }

    const float* Q  = qkv + (size_t)b * SEQ * QKVN + h * HDIM;
    const float* Kp = qkv + (size_t)b * SEQ * QKVN + DMODEL + h * HDIM;

    __shared__ float As[BKT][BM];
    __shared__ float Bs[BKT][BN];
    const int trow = tid / 16;
    const int tcol = tid % 16;

    float acc[8][8];
#pragma unroll
    for (int i = 0; i < 8; i++)
#pragma unroll
        for (int j = 0; j < 8; j++) acc[i][j] = 0.f;

    for (int k0 = 0; k0 < HDIM; k0 += BKT) {
#pragma unroll
        for (int u = 0; u < 2; u++) {
            int unit = tid + u * 256;
            int r = unit >> 2;
            int cv = (unit & 3) * 4;
            float4 v = *reinterpret_cast<const float4*>(Q + (size_t)(rowBase + r) * QKVN + k0 + cv);
            As[cv + 0][r] = v.x; As[cv + 1][r] = v.y;
            As[cv + 2][r] = v.z; As[cv + 3][r] = v.w;
            float4 w = *reinterpret_cast<const float4*>(Kp + (size_t)(colBase + r) * QKVN + k0 + cv);
            Bs[cv + 0][r] = w.x; Bs[cv + 1][r] = w.y;
            Bs[cv + 2][r] = w.z; Bs[cv + 3][r] = w.w;
        }
        __syncthreads();
#pragma unroll
        for (int k = 0; k < BKT; k++) {
            float a[8], b2[8];
#pragma unroll
            for (int i = 0; i < 8; i++) a[i] = As[k][trow * 8 + i];
#pragma unroll
            for (int j = 0; j < 8; j++) b2[j] = Bs[k][tcol * 8 + j];
#pragma unroll
            for (int i = 0; i < 8; i++)
#pragma unroll
                for (int j = 0; j < 8; j++)
                    acc[i][j] = fmaf(a[i], b2[j], acc[i][j]);
        }
        __syncthreads();
    }

    const float scale = 0.125f;  // 1/sqrt(64)
#pragma unroll
    for (int i = 0; i < 8; i++) {
        int r = rowBase + trow * 8 + i;
#pragma unroll
        for (int j = 0; j < 8; j++) {
            int c = colBase + tcol * 8 + j;
            float v = (c > r) ? -10000.f : acc[i][j] * scale;
            Cb[(size_t)r * SEQ + c] = v;
        }
    }
}

// ---------------------------------------------------------------------------
// Row softmax over SEQ=2048. One block (256 threads) per row.
// ---------------------------------------------------------------------------
__global__ __launch_bounds__(256) void softmax_kernel(float* __restrict__ scores)
{
    float* p = scores + (size_t)blockIdx.x * SEQ;
    const int tid = threadIdx.x;
    const int lane = tid & 31, warp = tid >> 5;
    __shared__ float red[8];

    float vals[8];
    float m = -CUDART_INF_F;
#pragma unroll
    for (int i = 0; i < 8; i++) {
        vals[i] = p[tid + i * 256];
        m = fmaxf(m, vals[i]);
    }
#pragma unroll
    for (int o = 16; o; o >>= 1) m = fmaxf(m, __shfl_xor_sync(0xffffffffu, m, o));
    if (lane == 0) red[warp] = m;
    __syncthreads();
    float mall = red[0];
#pragma unroll
    for (int i = 1; i < 8; i++) mall = fmaxf(mall, red[i]);
    __syncthreads();

    float s = 0.f;
#pragma unroll
    for (int i = 0; i < 8; i++) {
        vals[i] = __expf(vals[i] - mall);
        s += vals[i];
    }
#pragma unroll
    for (int o = 16; o; o >>= 1) s += __shfl_xor_sync(0xffffffffu, s, o);
    if (lane == 0) red[warp] = s;
    __syncthreads();
    float sall = 0.f;
#pragma unroll
    for (int i = 0; i < 8; i++) sall += red[i];
    float inv = 1.f / sall;
#pragma unroll
    for (int i = 0; i < 8; i++) p[tid + i * 256] = vals[i] * inv;
}

// ---------------------------------------------------------------------------
// PV: per (b,h): A[i,d] = sum_k P[i,k] * V[k,d]   (hd=64)
// K-loop truncated causally at rowBase+128 (P is exactly 0 beyond).
// BM=128, BN=64, BK=16, 256 threads, 8x4 per thread.
// Output written directly into merged-head layout [MROWS, DMODEL].
// ---------------------------------------------------------------------------
__global__ __launch_bounds__(256) void pv_kernel(
    const float* __restrict__ scores, const float* __restrict__ qkv,
    float* __restrict__ att)
{
    const int bh = blockIdx.z;
    const int b = bh / NHEAD, h = bh % NHEAD;
    const int rowBase = blockIdx.y * BM;
    const float* P = scores + (size_t)bh * SEQ * SEQ;
    const float* V = qkv + (size_t)b * SEQ * QKVN + 2 * DMODEL + h * HDIM;
    const int tid = threadIdx.x;
    const int trow = tid / 16;
    const int tcol = tid % 16;

    __shared__ float Ps[BKT][BM];
    __shared__ float Vs[BKT][HDIM];

    float acc[8][4];
#pragma unroll
    for (int i = 0; i < 8; i++)
#pragma unroll
        for (int j = 0; j < 4; j++) acc[i][j] = 0.f;

    const int kmax = rowBase + BM;   // causal: P[i,k]==0 for k>i
    for (int k0 = 0; k0 < kmax; k0 += BKT) {
        // P tile: 128 rows x 16 cols, transpose into Ps
#pragma unroll
        for (int u = 0; u < 2; u++) {
            int unit = tid + u * 256;
            int r = unit >> 2;
            int cv = (unit & 3) * 4;
            float4 v = *reinterpret_cast<const float4*>(P + (size_t)(rowBase + r) * SEQ + k0 + cv);
            Ps[cv + 0][r] = v.x; Ps[cv + 1][r] = v.y;
            Ps[cv + 2][r] = v.z; Ps[cv + 3][r] = v.w;
        }
        // V tile: 16 seq-rows x 64 dims
        {
            int r = tid >> 4;           // 0..15
            int c = (tid & 15) * 4;     // 0..60
            *reinterpret_cast<float4*>(&Vs[r][c]) =
                *reinterpret_cast<const float4*>(V + (size_t)(k0 + r) * QKVN + c);
        }
        __syncthreads();
#pragma unroll
        for (int k = 0; k < BKT; k++) {
            float a[8], b2[4];
#pragma unroll
            for (int i = 0; i < 8; i++) a[i] = Ps[k][trow * 8 + i];
#pragma unroll
            for (int j = 0; j < 4; j++) b2[j] = Vs[k][tcol * 4 + j];
#pragma unroll
            for (int i = 0; i < 8; i++)
#pragma unroll
                for (int j = 0; j < 4; j++)
                    acc[i][j] = fmaf(a[i], b2[j], acc[i][j]);
        }
        __syncthreads();
    }

#pragma unroll
    for (int i = 0; i < 8; i++) {
        int r = rowBase + trow * 8 + i;         // seq index within batch
        float4 o = make_float4(acc[i][0], acc[i][1], acc[i][2], acc[i][3]);
        *reinterpret_cast<float4*>(
            att + (size_t)(b * SEQ + r) * DMODEL + h * HDIM + tcol * 4) = o;
    }
}

// ---------------------------------------------------------------------------
extern "C" void kernel_launch(void* const* d_in, const int* in_sizes, int n_in,
                              void* d_out, int out_size)
{
    const float* x    = (const float*)d_in[0];
    const float* Wqkv = (const float*)d_in[1];
    const float* bqkv = (const float*)d_in[2];
    const float* Wp   = (const float*)d_in[3];
    const float* bp   = (const float*)d_in[4];
    // d_in[5] = causal mask, structurally known -> ignored
    float* out = (float*)d_out;

    float *qkv, *scores, *att;
    cudaGetSymbolAddress((void**)&qkv, g_qkv);
    cudaGetSymbolAddress((void**)&scores, g_scores);
    cudaGetSymbolAddress((void**)&att, g_att);

    // 1) QKV = x @ Wqkv + b     [8192,3072]
    {
        dim3 grid(QKVN / BN, MROWS / BM);
        sgemm_bias_kernel<<<grid, 256>>>(x, Wqkv, bqkv, qkv, MROWS, QKVN, DMODEL);
    }
    // 2) scores = Q K^T * scale, masked
    {
        dim3 grid(SEQ / BN, SEQ / BM, BH);
        scores_kernel<<<grid, 256>>>(qkv, scores);
    }
    // 3) softmax rows
    {
        softmax_kernel<<<BH * SEQ, 256>>>(scores);
    }
    // 4) att = P @ V   (merged-head layout)
    {
        dim3 grid(1, SEQ / BM, BH);
        pv_kernel<<<grid, 256>>>(scores, qkv, att);
    }
    // 5) out = att @ Wp + bp
    {
        dim3 grid(DMODEL / BN, MROWS / BM);
        sgemm_bias_kernel<<<grid, 256>>>(att, Wp, bp, out, MROWS, DMODEL, DMODEL);
    }
}

// round 2
// speedup vs baseline: 2.2085x; 2.2085x over previous
#include <cuda_runtime.h>
#include <cuda_bf16.h>
#include <math_constants.h>
#include <cstdint>

// Problem constants (fixed shapes for Attention_21801253995050)
#define Bsz 4
#define SEQ 2048
#define DMODEL 1024
#define NHEAD 16
#define HDIM 64
#define BH (Bsz * NHEAD)          // 64
#define MROWS (Bsz * SEQ)         // 8192
#define QKVN (3 * DMODEL)         // 3072

// Scratch (static device globals; no runtime allocation)
__device__ float g_qkv[MROWS * QKVN];
__device__ float g_scores[(size_t)BH * SEQ * SEQ];
__device__ float g_att[MROWS * DMODEL];

// ---------------------------------------------------------------------------
// tf32 helpers
// ---------------------------------------------------------------------------
__device__ __forceinline__ uint32_t f2tf32(float x) {
    uint32_t u;
    asm("cvt.rna.tf32.f32 %0, %1;" : "=r"(u) : "f"(x));
    return u;
}

__device__ __forceinline__ void mma_tf32(
    float& d0, float& d1, float& d2, float& d3,
    uint32_t a0, uint32_t a1, uint32_t a2, uint32_t a3,
    uint32_t b0, uint32_t b1)
{
    asm volatile(
        "mma.sync.aligned.m16n8k8.row.col.f32.tf32.tf32.f32 "
        "{%0,%1,%2,%3}, {%4,%5,%6,%7}, {%8,%9}, {%0,%1,%2,%3};\n"
        : "+f"(d0), "+f"(d1), "+f"(d2), "+f"(d3)
        : "r"(a0), "r"(a1), "r"(a2), "r"(a3), "r"(b0), "r"(b1));
}

#define BM 128
#define BN 128
#define BKT 16
#define AS_STRIDE 20    // BK + 4  -> conflict-free a-fragment loads
#define BS_STRIDE 136   // BN + 8  -> conflict-free b-fragment loads
#define VS_STRIDE 72    // 64 + 8

// ---------------------------------------------------------------------------
// tf32 GEMM + bias: C[M,N] = A[M,K] * B[K,N] + bias[N]
// 256 threads = 8 warps in 4(m) x 2(n); warp tile 32x64; mma m16n8k8.
// ---------------------------------------------------------------------------
__global__ __launch_bounds__(256) void sgemm_tf32_bias_kernel(
    const float* __restrict__ A, const float* __restrict__ B,
    const float* __restrict__ bias, float* __restrict__ C,
    int M, int N, int K)
{
    __shared__ uint32_t As[BM][AS_STRIDE];      // [m][k] tf32 bits
    __shared__ uint32_t Bs[BKT][BS_STRIDE];     // [k][n] tf32 bits

    const int tid  = threadIdx.x;
    const int warp = tid >> 5;
    const int lane = tid & 31;
    const int grp  = lane >> 2;     // 0..7
    const int qid  = lane & 3;      // 0..3
    const int wm   = warp & 3;      // 0..3  (rows)
    const int wn   = warp >> 2;     // 0..1  (cols)
    const int rowBase = blockIdx.y * BM;
    const int colBase = blockIdx.x * BN;

    float acc[2][8][4];
#pragma unroll
    for (int i = 0; i < 2; i++)
#pragma unroll
        for (int j = 0; j < 8; j++)
#pragma unroll
            for (int v = 0; v < 4; v++) acc[i][j][v] = 0.f;

    // A tile loader mapping: thread t -> row t/2, cols (t%2)*8 .. +7
    const int la_r = tid >> 1;
    const int la_c = (tid & 1) * 8;
    // B tile loader mapping: thread t -> row t/16, cols (t%16)*8 .. +7
    const int lb_r = tid >> 4;
    const int lb_c = (tid & 15) * 8;

    for (int k0 = 0; k0 < K; k0 += BKT) {
        // load A tile (128 x 16)
        {
            const float* src = A + (size_t)(rowBase + la_r) * K + k0 + la_c;
            float4 v0 = *reinterpret_cast<const float4*>(src);
            float4 v1 = *reinterpret_cast<const float4*>(src + 4);
            As[la_r][la_c + 0] = f2tf32(v0.x); As[la_r][la_c + 1] = f2tf32(v0.y);
            As[la_r][la_c + 2] = f2tf32(v0.z); As[la_r][la_c + 3] = f2tf32(v0.w);
            As[la_r][la_c + 4] = f2tf32(v1.x); As[la_r][la_c + 5] = f2tf32(v1.y);
            As[la_r][la_c + 6] = f2tf32(v1.z); As[la_r][la_c + 7] = f2tf32(v1.w);
        }
        // load B tile (16 x 128)
        {
            const float* src = B + (size_t)(k0 + lb_r) * N + colBase + lb_c;
            float4 v0 = *reinterpret_cast<const float4*>(src);
            float4 v1 = *reinterpret_cast<const float4*>(src + 4);
            Bs[lb_r][lb_c + 0] = f2tf32(v0.x); Bs[lb_r][lb_c + 1] = f2tf32(v0.y);
            Bs[lb_r][lb_c + 2] = f2tf32(v0.z); Bs[lb_r][lb_c + 3] = f2tf32(v0.w);
            Bs[lb_r][lb_c + 4] = f2tf32(v1.x); Bs[lb_r][lb_c + 5] = f2tf32(v1.y);
            Bs[lb_r][lb_c + 6] = f2tf32(v1.z); Bs[lb_r][lb_c + 7] = f2tf32(v1.w);
        }
        __syncthreads();

#pragma unroll
        for (int s = 0; s < 2; s++) {
            const int ks = s * 8;
            uint32_t af[2][4];
#pragma unroll
            for (int mt = 0; mt < 2; mt++) {
                int rb = wm * 32 + mt * 16;
                af[mt][0] = As[rb + grp][ks + qid];
                af[mt][1] = As[rb + grp + 8][ks + qid];
                af[mt][2] = As[rb + grp][ks + qid + 4];
                af[mt][3] = As[rb + grp + 8][ks + qid + 4];
            }
#pragma unroll
            for (int nt = 0; nt < 8; nt++) {
                int cb = wn * 64 + nt * 8;
                uint32_t b0 = Bs[ks + qid][cb + grp];
                uint32_t b1 = Bs[ks + qid + 4][cb + grp];
#pragma unroll
                for (int mt = 0; mt < 2; mt++) {
                    mma_tf32(acc[mt][nt][0], acc[mt][nt][1], acc[mt][nt][2], acc[mt][nt][3],
                             af[mt][0], af[mt][1], af[mt][2], af[mt][3], b0, b1);
                }
            }
        }
        __syncthreads();
    }

#pragma unroll
    for (int mt = 0; mt < 2; mt++) {
#pragma unroll
        for (int nt = 0; nt < 8; nt++) {
            int c = colBase + wn * 64 + nt * 8 + 2 * qid;
            float bx = bias[c], by = bias[c + 1];
            int r0 = rowBase + wm * 32 + mt * 16 + grp;
            float2 o0 = make_float2(acc[mt][nt][0] + bx, acc[mt][nt][1] + by);
            *reinterpret_cast<float2*>(C + (size_t)r0 * N + c) = o0;
            float2 o1 = make_float2(acc[mt][nt][2] + bx, acc[mt][nt][3] + by);
            *reinterpret_cast<float2*>(C + (size_t)(r0 + 8) * N + c) = o1;
        }
    }
}

// ---------------------------------------------------------------------------
// Scores (tf32): S[i,j] = (Q_i . K_j) * 0.125 for j<=i; masked tiles skipped,
// masked entries inside diagonal tiles NOT written (softmax zero-fills).
// ---------------------------------------------------------------------------
__global__ __launch_bounds__(256) void scores_tf32_kernel(
    const float* __restrict__ qkv, float* __restrict__ scores)
{
    const int rowBase = blockIdx.y * BM;
    const int colBase = blockIdx.x * BN;
    if (colBase > rowBase) return;   // fully masked tile: nothing to do

    const int bh = blockIdx.z;
    const int b = bh / NHEAD, h = bh % NHEAD;
    float* Cb = scores + (size_t)bh * SEQ * SEQ;
    const float* Q  = qkv + (size_t)b * SEQ * QKVN + h * HDIM;
    const float* Kp = qkv + (size_t)b * SEQ * QKVN + DMODEL + h * HDIM;

    __shared__ uint32_t As[BM][AS_STRIDE];
    __shared__ uint32_t Bs[BKT][BS_STRIDE];

    const int tid  = threadIdx.x;
    const int warp = tid >> 5;
    const int lane = tid & 31;
    const int grp  = lane >> 2;
    const int qid  = lane & 3;
    const int wm   = warp & 3;
    const int wn   = warp >> 2;

    float acc[2][8][4];
#pragma unroll
    for (int i = 0; i < 2; i++)
#pragma unroll
        for (int j = 0; j < 8; j++)
#pragma unroll
            for (int v = 0; v < 4; v++) acc[i][j][v] = 0.f;

    const int la_r = tid >> 1;
    const int la_c = (tid & 1) * 8;

    for (int k0 = 0; k0 < HDIM; k0 += BKT) {
        // Q tile (128 x 16)
        {
            const float* src = Q + (size_t)(rowBase + la_r) * QKVN + k0 + la_c;
            float4 v0 = *reinterpret_cast<const float4*>(src);
            float4 v1 = *reinterpret_cast<const float4*>(src + 4);
            As[la_r][la_c + 0] = f2tf32(v0.x); As[la_r][la_c + 1] = f2tf32(v0.y);
            As[la_r][la_c + 2] = f2tf32(v0.z); As[la_r][la_c + 3] = f2tf32(v0.w);
            As[la_r][la_c + 4] = f2tf32(v1.x); As[la_r][la_c + 5] = f2tf32(v1.y);
            As[la_r][la_c + 6] = f2tf32(v1.z); As[la_r][la_c + 7] = f2tf32(v1.w);
        }
        // K tile transposed: Bs[k][n] = K[colBase+n][k0+k]
        {
            const float* src = Kp + (size_t)(colBase + la_r) * QKVN + k0 + la_c;
            float4 v0 = *reinterpret_cast<const float4*>(src);
            float4 v1 = *reinterpret_cast<const float4*>(src + 4);
            Bs[la_c + 0][la_r] = f2tf32(v0.x); Bs[la_c + 1][la_r] = f2tf32(v0.y);
            Bs[la_c + 2][la_r] = f2tf32(v0.z); Bs[la_c + 3][la_r] = f2tf32(v0.w);
            Bs[la_c + 4][la_r] = f2tf32(v1.x); Bs[la_c + 5][la_r] = f2tf32(v1.y);
            Bs[la_c + 6][la_r] = f2tf32(v1.z); Bs[la_c + 7][la_r] = f2tf32(v1.w);
        }
        __syncthreads();

#pragma unroll
        for (int s = 0; s < 2; s++) {
            const int ks = s * 8;
            uint32_t af[2][4];
#pragma unroll
            for (int mt = 0; mt < 2; mt++) {
                int rb = wm * 32 + mt * 16;
                af[mt][0] = As[rb + grp][ks + qid];
                af[mt][1] = As[rb + grp + 8][ks + qid];
                af[mt][2] = As[rb + grp][ks + qid + 4];
                af[mt][3] = As[rb + grp + 8][ks + qid + 4];
            }
#pragma unroll
            for (int nt = 0; nt < 8; nt++) {
                int cb = wn * 64 + nt * 8;
                uint32_t b0 = Bs[ks + qid][cb + grp];
                uint32_t b1 = Bs[ks + qid + 4][cb + grp];
#pragma unroll
                for (int mt = 0; mt < 2; mt++) {
                    mma_tf32(acc[mt][nt][0], acc[mt][nt][1], acc[mt][nt][2], acc[mt][nt][3],
                             af[mt][0], af[mt][1], af[mt][2], af[mt][3], b0, b1);
                }
            }
        }
        __syncthreads();
    }

    const float scale = 0.125f;
    const bool interior = (colBase + BN - 1) <= rowBase;  // whole tile valid
#pragma unroll
    for (int mt = 0; mt < 2; mt++) {
#pragma unroll
        for (int nt = 0; nt < 8; nt++) {
            int c = colBase + wn * 64 + nt * 8 + 2 * qid;
            int r0 = rowBase + wm * 32 + mt * 16 + grp;
            int r1 = r0 + 8;
            if (interior) {
                float2 o0 = make_float2(acc[mt][nt][0] * scale, acc[mt][nt][1] * scale);
                *reinterpret_cast<float2*>(Cb + (size_t)r0 * SEQ + c) = o0;
                float2 o1 = make_float2(acc[mt][nt][2] * scale, acc[mt][nt][3] * scale);
                *reinterpret_cast<float2*>(Cb + (size_t)r1 * SEQ + c) = o1;
            } else {
                if (c <= r0)     Cb[(size_t)r0 * SEQ + c]     = acc[mt][nt][0] * scale;
                if (c + 1 <= r0) Cb[(size_t)r0 * SEQ + c + 1] = acc[mt][nt][1] * scale;
                if (c <= r1)     Cb[(size_t)r1 * SEQ + c]     = acc[mt][nt][2] * scale;
                if (c + 1 <= r1) Cb[(size_t)r1 * SEQ + c + 1] = acc[mt][nt][3] * scale;
            }
        }
    }
}

// ---------------------------------------------------------------------------
// Variable-length softmax. Row i: valid j in [0, i]; writes zeros for
// j in (i, kmax) where kmax = ceil128(i+1) so PV can read a rectangular block.
// ---------------------------------------------------------------------------
__global__ __launch_bounds__(256) void softmax_kernel(float* __restrict__ scores)
{
    const int row = blockIdx.x;
    const int i = row & (SEQ - 1);
    float* p = scores + (size_t)row * SEQ;
    const int kmax = ((i >> 7) + 1) << 7;
    const int tid = threadIdx.x;
    const int lane = tid & 31, warp = tid >> 5;
    __shared__ float red[8];

    float vals[8];
    float m = -CUDART_INF_F;
#pragma unroll
    for (int u = 0; u < 8; u++) {
        int c = tid + u * 256;
        vals[u] = -CUDART_INF_F;
        if (c < kmax && c <= i) { vals[u] = p[c]; m = fmaxf(m, vals[u]); }
    }
#pragma unroll
    for (int o = 16; o; o >>= 1) m = fmaxf(m, __shfl_xor_sync(0xffffffffu, m, o));
    if (lane == 0) red[warp] = m;
    __syncthreads();
    float mall = red[0];
#pragma unroll
    for (int u = 1; u < 8; u++) mall = fmaxf(mall, red[u]);
    __syncthreads();

    float s = 0.f;
#pragma unroll
    for (int u = 0; u < 8; u++) {
        vals[u] = __expf(vals[u] - mall);   // exp(-inf - m) = 0
        s += vals[u];
    }
#pragma unroll
    for (int o = 16; o; o >>= 1) s += __shfl_xor_sync(0xffffffffu, s, o);
    if (lane == 0) red[warp] = s;
    __syncthreads();
    float sall = 0.f;
#pragma unroll
    for (int u = 0; u < 8; u++) sall += red[u];
    float inv = 1.f / sall;
#pragma unroll
    for (int u = 0; u < 8; u++) {
        int c = tid + u * 256;
        if (c < kmax) p[c] = vals[u] * inv;
    }
}

// ---------------------------------------------------------------------------
// PV (tf32): A[i,d] = sum_k P[i,k] * V[k,d], hd=64, causal K truncation.
// 8 warps in 4(m) x 2(n); warp tile 32x32.
// ---------------------------------------------------------------------------
__global__ __launch_bounds__(256) void pv_tf32_kernel(
    const float* __restrict__ scores, const float* __restrict__ qkv,
    float* __restrict__ att)
{
    const int bh = blockIdx.z;
    const int b = bh / NHEAD, h = bh % NHEAD;
    const int rowBase = blockIdx.y * BM;
    const float* P = scores + (size_t)bh * SEQ * SEQ;
    const float* V = qkv + (size_t)b * SEQ * QKVN + 2 * DMODEL + h * HDIM;

    __shared__ uint32_t Ps[BM][AS_STRIDE];
    __shared__ uint32_t Vs[BKT][VS_STRIDE];

    const int tid  = threadIdx.x;
    const int warp = tid >> 5;
    const int lane = tid & 31;
    const int grp  = lane >> 2;
    const int qid  = lane & 3;
    const int wm   = warp & 3;
    const int wn   = warp >> 2;

    float acc[2][4][4];
#pragma unroll
    for (int i = 0; i < 2; i++)
#pragma unroll
        for (int j = 0; j < 4; j++)
#pragma unroll
            for (int v = 0; v < 4; v++) acc[i][j][v] = 0.f;

    const int la_r = tid >> 1;
    const int la_c = (tid & 1) * 8;
    const int lv_r = tid >> 4;          // 0..15
    const int lv_c = (tid & 15) * 4;    // 0..60

    const int kmaxb = rowBase + BM;
    for (int k0 = 0; k0 < kmaxb; k0 += BKT) {
        // P tile (128 x 16)
        {
            const float* src = P + (size_t)(rowBase + la_r) * SEQ + k0 + la_c;
            float4 v0 = *reinterpret_cast<const float4*>(src);
            float4 v1 = *reinterpret_cast<const float4*>(src + 4);
            Ps[la_r][la_c + 0] = f2tf32(v0.x); Ps[la_r][la_c + 1] = f2tf32(v0.y);
            Ps[la_r][la_c + 2] = f2tf32(v0.z); Ps[la_r][la_c + 3] = f2tf32(v0.w);
            Ps[la_r][la_c + 4] = f2tf32(v1.x); Ps[la_r][la_c + 5] = f2tf32(v1.y);
            Ps[la_r][la_c + 6] = f2tf32(v1.z); Ps[la_r][la_c + 7] = f2tf32(v1.w);
        }
        // V tile (16 x 64)
        {
            const float* src = V + (size_t)(k0 + lv_r) * QKVN + lv_c;
            float4 v0 = *reinterpret_cast<const float4*>(src);
            Vs[lv_r][lv_c + 0] = f2tf32(v0.x); Vs[lv_r][lv_c + 1] = f2tf32(v0.y);
            Vs[lv_r][lv_c + 2] = f2tf32(v0.z); Vs[lv_r][lv_c + 3] = f2tf32(v0.w);
        }
        __syncthreads();

#pragma unroll
        for (int s = 0; s < 2; s++) {
            const int ks = s * 8;
            uint32_t af[2][4];
#pragma unroll
            for (int mt = 0; mt < 2; mt++) {
                int rb = wm * 32 + mt * 16;
                af[mt][0] = Ps[rb + grp][ks + qid];
                af[mt][1] = Ps[rb + grp + 8][ks + qid];
                af[mt][2] = Ps[rb + grp][ks + qid + 4];
                af[mt][3] = Ps[rb + grp + 8][ks + qid + 4];
            }
#pragma unroll
            for (int nt = 0; nt < 4; nt++) {
                int cb = wn * 32 + nt * 8;
                uint32_t b0 = Vs[ks + qid][cb + grp];
                uint32_t b1 = Vs[ks + qid + 4][cb + grp];
#pragma unroll
                for (int mt = 0; mt < 2; mt++) {
                    mma_tf32(acc[mt][nt][0], acc[mt][nt][1], acc[mt][nt][2], acc[mt][nt][3],
                             af[mt][0], af[mt][1], af[mt][2], af[mt][3], b0, b1);
                }
            }
        }
        __syncthreads();
    }

#pragma unroll
    for (int mt = 0; mt < 2; mt++) {
#pragma unroll
        for (int nt = 0; nt < 4; nt++) {
            int cc = wn * 32 + nt * 8 + 2 * qid;       // 0..62 within head
            int r0 = rowBase + wm * 32 + mt * 16 + grp;
            float2 o0 = make_float2(acc[mt][nt][0], acc[mt][nt][1]);
            *reinterpret_cast<float2*>(
                att + (size_t)(b * SEQ + r0) * DMODEL + h * HDIM + cc) = o0;
            float2 o1 = make_float2(acc[mt][nt][2], acc[mt][nt][3]);
            *reinterpret_cast<float2*>(
                att + (size_t)(b * SEQ + r0 + 8) * DMODEL + h * HDIM + cc) = o1;
        }
    }
}

// ---------------------------------------------------------------------------
extern "C" void kernel_launch(void* const* d_in, const int* in_sizes, int n_in,
                              void* d_out, int out_size)
{
    const float* x    = (const float*)d_in[0];
    const float* Wqkv = (const float*)d_in[1];
    const float* bqkv = (const float*)d_in[2];
    const float* Wp   = (const float*)d_in[3];
    const float* bp   = (const float*)d_in[4];
    float* out = (float*)d_out;

    float *qkv, *scores, *att;
    cudaGetSymbolAddress((void**)&qkv, g_qkv);
    cudaGetSymbolAddress((void**)&scores, g_scores);
    cudaGetSymbolAddress((void**)&att, g_att);

    // 1) QKV = x @ Wqkv + b
    {
        dim3 grid(QKVN / BN, MROWS / BM);
        sgemm_tf32_bias_kernel<<<grid, 256>>>(x, Wqkv, bqkv, qkv, MROWS, QKVN, DMODEL);
    }
    // 2) scores = Q K^T * scale (lower triangle only)
    {
        dim3 grid(SEQ / BN, SEQ / BM, BH);
        scores_tf32_kernel<<<grid, 256>>>(qkv, scores);
    }
    // 3) variable-length softmax
    {
        softmax_kernel<<<BH * SEQ, 256>>>(scores);
    }
    // 4) att = P @ V
    {
        dim3 grid(1, SEQ / BM, BH);
        pv_tf32_kernel<<<grid, 256>>>(scores, qkv, att);
    }
    // 5) out = att @ Wp + bp
    {
        dim3 grid(DMODEL / BN, MROWS / BM);
        sgemm_tf32_bias_kernel<<<grid, 256>>>(att, Wp, bp, out, MROWS, DMODEL, DMODEL);
    }
}

// round 3
// speedup vs baseline: 3.2121x; 1.4544x over previous
#include <cuda_runtime.h>
#include <cuda_bf16.h>
#include <math_constants.h>
#include <cstdint>

#define Bsz 4
#define SEQ 2048
#define DMODEL 1024
#define NHEAD 16
#define HDIM 64
#define BH (Bsz * NHEAD)          // 64
#define MROWS (Bsz * SEQ)         // 8192
#define QKVN (3 * DMODEL)         // 3072

__device__ float g_qkv[MROWS * QKVN];
__device__ float g_att[MROWS * DMODEL];

__device__ __forceinline__ uint32_t f2tf32(float x) {
    uint32_t u;
    asm("cvt.rna.tf32.f32 %0, %1;" : "=r"(u) : "f"(x));
    return u;
}

__device__ __forceinline__ void mma_tf32(
    float& d0, float& d1, float& d2, float& d3,
    uint32_t a0, uint32_t a1, uint32_t a2, uint32_t a3,
    uint32_t b0, uint32_t b1)
{
    asm volatile(
        "mma.sync.aligned.m16n8k8.row.col.f32.tf32.tf32.f32 "
        "{%0,%1,%2,%3}, {%4,%5,%6,%7}, {%8,%9}, {%0,%1,%2,%3};\n"
        : "+f"(d0), "+f"(d1), "+f"(d2), "+f"(d3)
        : "r"(a0), "r"(a1), "r"(a2), "r"(a3), "r"(b0), "r"(b1));
}

#define BM 128
#define BN 128
#define BKT 16
#define AS_STRIDE 20
#define BS_STRIDE 136

// ---------------------------------------------------------------------------
// Double-buffered tf32 GEMM + bias: C = A*B + bias
// ---------------------------------------------------------------------------
__global__ __launch_bounds__(256) void sgemm_tf32_bias_kernel(
    const float* __restrict__ A, const float* __restrict__ B,
    const float* __restrict__ bias, float* __restrict__ C,
    int M, int N, int K)
{
    __shared__ uint32_t As[2][BM][AS_STRIDE];
    __shared__ uint32_t Bs[2][BKT][BS_STRIDE];

    const int tid  = threadIdx.x;
    const int warp = tid >> 5;
    const int lane = tid & 31;
    const int grp  = lane >> 2;
    const int qid  = lane & 3;
    const int wm   = warp & 3;
    const int wn   = warp >> 2;
    const int rowBase = blockIdx.y * BM;
    const int colBase = blockIdx.x * BN;

    const int la_r = tid >> 1;
    const int la_c = (tid & 1) * 8;
    const int lb_r = tid >> 4;
    const int lb_c = (tid & 15) * 8;

    const float* Aptr = A + (size_t)(rowBase + la_r) * K + la_c;
    const float* Bptr = B + (size_t)lb_r * N + colBase + lb_c;

    float acc[2][8][4];
#pragma unroll
    for (int i = 0; i < 2; i++)
#pragma unroll
        for (int j = 0; j < 8; j++)
#pragma unroll
            for (int v = 0; v < 4; v++) acc[i][j][v] = 0.f;

    float4 fa0, fa1, fb0, fb1;
    fa0 = *reinterpret_cast<const float4*>(Aptr);
    fa1 = *reinterpret_cast<const float4*>(Aptr + 4);
    fb0 = *reinterpret_cast<const float4*>(Bptr);
    fb1 = *reinterpret_cast<const float4*>(Bptr + 4);
    {
        As[0][la_r][la_c + 0] = f2tf32(fa0.x); As[0][la_r][la_c + 1] = f2tf32(fa0.y);
        As[0][la_r][la_c + 2] = f2tf32(fa0.z); As[0][la_r][la_c + 3] = f2tf32(fa0.w);
        As[0][la_r][la_c + 4] = f2tf32(fa1.x); As[0][la_r][la_c + 5] = f2tf32(fa1.y);
        As[0][la_r][la_c + 6] = f2tf32(fa1.z); As[0][la_r][la_c + 7] = f2tf32(fa1.w);
        Bs[0][lb_r][lb_c + 0] = f2tf32(fb0.x); Bs[0][lb_r][lb_c + 1] = f2tf32(fb0.y);
        Bs[0][lb_r][lb_c + 2] = f2tf32(fb0.z); Bs[0][lb_r][lb_c + 3] = f2tf32(fb0.w);
        Bs[0][lb_r][lb_c + 4] = f2tf32(fb1.x); Bs[0][lb_r][lb_c + 5] = f2tf32(fb1.y);
        Bs[0][lb_r][lb_c + 6] = f2tf32(fb1.z); Bs[0][lb_r][lb_c + 7] = f2tf32(fb1.w);
    }
    __syncthreads();

    const int NT = K / BKT;
    for (int kt = 0; kt < NT; kt++) {
        const int cur = kt & 1;
        if (kt + 1 < NT) {
            const float* ap = Aptr + (kt + 1) * BKT;
            fa0 = *reinterpret_cast<const float4*>(ap);
            fa1 = *reinterpret_cast<const float4*>(ap + 4);
            const float* bp = Bptr + (size_t)(kt + 1) * BKT * N;
            fb0 = *reinterpret_cast<const float4*>(bp);
            fb1 = *reinterpret_cast<const float4*>(bp + 4);
        }
#pragma unroll
        for (int s = 0; s < 2; s++) {
            const int ks = s * 8;
            uint32_t af[2][4];
#pragma unroll
            for (int mt = 0; mt < 2; mt++) {
                int rb = wm * 32 + mt * 16;
                af[mt][0] = As[cur][rb + grp][ks + qid];
                af[mt][1] = As[cur][rb + grp + 8][ks + qid];
                af[mt][2] = As[cur][rb + grp][ks + qid + 4];
                af[mt][3] = As[cur][rb + grp + 8][ks + qid + 4];
            }
#pragma unroll
            for (int nt = 0; nt < 8; nt++) {
                int cb = wn * 64 + nt * 8;
                uint32_t b0 = Bs[cur][ks + qid][cb + grp];
                uint32_t b1 = Bs[cur][ks + qid + 4][cb + grp];
#pragma unroll
                for (int mt = 0; mt < 2; mt++) {
                    mma_tf32(acc[mt][nt][0], acc[mt][nt][1], acc[mt][nt][2], acc[mt][nt][3],
                             af[mt][0], af[mt][1], af[mt][2], af[mt][3], b0, b1);
                }
            }
        }
        if (kt + 1 < NT) {
            const int nxt = cur ^ 1;
            As[nxt][la_r][la_c + 0] = f2tf32(fa0.x); As[nxt][la_r][la_c + 1] = f2tf32(fa0.y);
            As[nxt][la_r][la_c + 2] = f2tf32(fa0.z); As[nxt][la_r][la_c + 3] = f2tf32(fa0.w);
            As[nxt][la_r][la_c + 4] = f2tf32(fa1.x); As[nxt][la_r][la_c + 5] = f2tf32(fa1.y);
            As[nxt][la_r][la_c + 6] = f2tf32(fa1.z); As[nxt][la_r][la_c + 7] = f2tf32(fa1.w);
            Bs[nxt][lb_r][lb_c + 0] = f2tf32(fb0.x); Bs[nxt][lb_r][lb_c + 1] = f2tf32(fb0.y);
            Bs[nxt][lb_r][lb_c + 2] = f2tf32(fb0.z); Bs[nxt][lb_r][lb_c + 3] = f2tf32(fb0.w);
            Bs[nxt][lb_r][lb_c + 4] = f2tf32(fb1.x); Bs[nxt][lb_r][lb_c + 5] = f2tf32(fb1.y);
            Bs[nxt][lb_r][lb_c + 6] = f2tf32(fb1.z); Bs[nxt][lb_r][lb_c + 7] = f2tf32(fb1.w);
            __syncthreads();
        }
    }

#pragma unroll
    for (int mt = 0; mt < 2; mt++) {
#pragma unroll
        for (int nt = 0; nt < 8; nt++) {
            int c = colBase + wn * 64 + nt * 8 + 2 * qid;
            float bx = bias[c], by = bias[c + 1];
            int r0 = rowBase + wm * 32 + mt * 16 + grp;
            float2 o0 = make_float2(acc[mt][nt][0] + bx, acc[mt][nt][1] + by);
            *reinterpret_cast<float2*>(C + (size_t)r0 * N + c) = o0;
            float2 o1 = make_float2(acc[mt][nt][2] + bx, acc[mt][nt][3] + by);
            *reinterpret_cast<float2*>(C + (size_t)(r0 + 8) * N + c) = o1;
        }
    }
}

// ---------------------------------------------------------------------------
// Fused flash attention (tf32). One CTA = one (b,h) x 128 query rows.
// 8 warps, warp = 16 q rows. Online softmax; P round-trips through smem
// (warp-private rows -> no extra sync).
// smem (words): Ks[64][136] | Vs[128][72] | Ps[128][132]
// ---------------------------------------------------------------------------
#define KS_STRIDE 136
#define VS_STRIDE 72
#define PS_STRIDE 132
#define KS_OFF 0
#define VS_OFF (64 * KS_STRIDE)                       // 8704
#define PS_OFF (VS_OFF + 128 * VS_STRIDE)             // 17920
#define FA_SMEM_WORDS (PS_OFF + 128 * PS_STRIDE)      // 34816
#define FA_SMEM_BYTES (FA_SMEM_WORDS * 4)             // 139264

__global__ __launch_bounds__(256) void fa_kernel(
    const float* __restrict__ qkv, float* __restrict__ att)
{
    extern __shared__ uint32_t smw[];
    uint32_t* Ks = smw + KS_OFF;
    uint32_t* Vs = smw + VS_OFF;
    uint32_t* Ps = smw + PS_OFF;

    const int qb = 15 - blockIdx.x;      // longest blocks first
    const int bh = blockIdx.y;
    const int b = bh >> 4, h = bh & 15;
    const float* Qp = qkv + (size_t)b * SEQ * QKVN + h * HDIM;
    const float* Kp = Qp + DMODEL;
    const float* Vp = Qp + 2 * DMODEL;

    const int tid = threadIdx.x, warp = tid >> 5, lane = tid & 31;
    const int grp = lane >> 2, qid = lane & 3;
    const int la_r = tid >> 1;
    const int la_c = (tid & 1) * 8;

    // ---- Stage Q (scaled) transposed into Ks area, pull A-fragments ----
    {
        const float* src = Qp + (size_t)(qb * 128 + la_r) * QKVN + la_c;
#pragma unroll
        for (int k0 = 0; k0 < HDIM; k0 += 16) {
            float4 v0 = *reinterpret_cast<const float4*>(src + k0);
            float4 v1 = *reinterpret_cast<const float4*>(src + k0 + 4);
            Ks[(k0 + la_c + 0) * KS_STRIDE + la_r] = f2tf32(v0.x * 0.125f);
            Ks[(k0 + la_c + 1) * KS_STRIDE + la_r] = f2tf32(v0.y * 0.125f);
            Ks[(k0 + la_c + 2) * KS_STRIDE + la_r] = f2tf32(v0.z * 0.125f);
            Ks[(k0 + la_c + 3) * KS_STRIDE + la_r] = f2tf32(v0.w * 0.125f);
            Ks[(k0 + la_c + 4) * KS_STRIDE + la_r] = f2tf32(v1.x * 0.125f);
            Ks[(k0 + la_c + 5) * KS_STRIDE + la_r] = f2tf32(v1.y * 0.125f);
            Ks[(k0 + la_c + 6) * KS_STRIDE + la_r] = f2tf32(v1.z * 0.125f);
            Ks[(k0 + la_c + 7) * KS_STRIDE + la_r] = f2tf32(v1.w * 0.125f);
        }
    }
    __syncthreads();
    uint32_t aq[8][4];
    {
        const int m0 = warp * 16 + grp;
#pragma unroll
        for (int k = 0; k < 8; k++) {
            aq[k][0] = Ks[(8 * k + qid) * KS_STRIDE + m0];
            aq[k][1] = Ks[(8 * k + qid) * KS_STRIDE + m0 + 8];
            aq[k][2] = Ks[(8 * k + qid + 4) * KS_STRIDE + m0];
            aq[k][3] = Ks[(8 * k + qid + 4) * KS_STRIDE + m0 + 8];
        }
    }

    float m0v = -CUDART_INF_F, m1v = -CUDART_INF_F;
    float l0 = 0.f, l1 = 0.f;
    float acc_o[8][4];
#pragma unroll
    for (int j = 0; j < 8; j++)
#pragma unroll
        for (int v = 0; v < 4; v++) acc_o[j][v] = 0.f;

    for (int kb = 0; kb <= qb; kb++) {
        __syncthreads();   // everyone done with Ks (Q frags / prev K) and Vs
        // load K block transposed: Ks[d][n] = K[kb*128+n][d]
        {
            const float* src = Kp + (size_t)(kb * 128 + la_r) * QKVN + la_c;
#pragma unroll
            for (int k0 = 0; k0 < HDIM; k0 += 16) {
                float4 v0 = *reinterpret_cast<const float4*>(src + k0);
                float4 v1 = *reinterpret_cast<const float4*>(src + k0 + 4);
                Ks[(k0 + la_c + 0) * KS_STRIDE + la_r] = f2tf32(v0.x);
                Ks[(k0 + la_c + 1) * KS_STRIDE + la_r] = f2tf32(v0.y);
                Ks[(k0 + la_c + 2) * KS_STRIDE + la_r] = f2tf32(v0.z);
                Ks[(k0 + la_c + 3) * KS_STRIDE + la_r] = f2tf32(v0.w);
                Ks[(k0 + la_c + 4) * KS_STRIDE + la_r] = f2tf32(v1.x);
                Ks[(k0 + la_c + 5) * KS_STRIDE + la_r] = f2tf32(v1.y);
                Ks[(k0 + la_c + 6) * KS_STRIDE + la_r] = f2tf32(v1.z);
                Ks[(k0 + la_c + 7) * KS_STRIDE + la_r] = f2tf32(v1.w);
            }
        }
        // load V block: Vs[k][d] = V[kb*128+k][d]
        {
#pragma unroll
            for (int rep = 0; rep < 8; rep++) {
                int unit = tid + rep * 256;
                int row = unit >> 4;
                int f4  = unit & 15;
                float4 v = *reinterpret_cast<const float4*>(
                    Vp + (size_t)(kb * 128 + row) * QKVN + 4 * f4);
                Vs[row * VS_STRIDE + 4 * f4 + 0] = f2tf32(v.x);
                Vs[row * VS_STRIDE + 4 * f4 + 1] = f2tf32(v.y);
                Vs[row * VS_STRIDE + 4 * f4 + 2] = f2tf32(v.z);
                Vs[row * VS_STRIDE + 4 * f4 + 3] = f2tf32(v.w);
            }
        }
        __syncthreads();

        // ---- S = Q K^T ----
        float s_[16][4];
#pragma unroll
        for (int nt = 0; nt < 16; nt++)
#pragma unroll
            for (int v = 0; v < 4; v++) s_[nt][v] = 0.f;
#pragma unroll
        for (int k = 0; k < 8; k++) {
#pragma unroll
            for (int nt = 0; nt < 16; nt++) {
                uint32_t b0 = Ks[(8 * k + qid) * KS_STRIDE + nt * 8 + grp];
                uint32_t b1 = Ks[(8 * k + qid + 4) * KS_STRIDE + nt * 8 + grp];
                mma_tf32(s_[nt][0], s_[nt][1], s_[nt][2], s_[nt][3],
                         aq[k][0], aq[k][1], aq[k][2], aq[k][3], b0, b1);
            }
        }

        // ---- causal mask on diagonal block ----
        if (kb == qb) {
            const int r0 = warp * 16 + grp, r1 = r0 + 8;
#pragma unroll
            for (int nt = 0; nt < 16; nt++) {
                int c = nt * 8 + 2 * qid;
                if (c > r0)     s_[nt][0] = -CUDART_INF_F;
                if (c + 1 > r0) s_[nt][1] = -CUDART_INF_F;
                if (c > r1)     s_[nt][2] = -CUDART_INF_F;
                if (c + 1 > r1) s_[nt][3] = -CUDART_INF_F;
            }
        }

        // ---- online softmax ----
        float mx0 = -CUDART_INF_F, mx1 = -CUDART_INF_F;
#pragma unroll
        for (int nt = 0; nt < 16; nt++) {
            mx0 = fmaxf(mx0, fmaxf(s_[nt][0], s_[nt][1]));
            mx1 = fmaxf(mx1, fmaxf(s_[nt][2], s_[nt][3]));
        }
        mx0 = fmaxf(mx0, __shfl_xor_sync(0xffffffffu, mx0, 1));
        mx0 = fmaxf(mx0, __shfl_xor_sync(0xffffffffu, mx0, 2));
        mx1 = fmaxf(mx1, __shfl_xor_sync(0xffffffffu, mx1, 1));
        mx1 = fmaxf(mx1, __shfl_xor_sync(0xffffffffu, mx1, 2));

        float mn0 = fmaxf(m0v, mx0), mn1 = fmaxf(m1v, mx1);
        float a0 = __expf(m0v - mn0), a1 = __expf(m1v - mn1);

        const int pr0 = (warp * 16 + grp) * PS_STRIDE;
        const int pr1 = pr0 + 8 * PS_STRIDE;
        float sum0 = 0.f, sum1 = 0.f;
#pragma unroll
        for (int nt = 0; nt < 16; nt++) {
            int c = nt * 8 + 2 * qid;
            float p0 = __expf(s_[nt][0] - mn0);
            float p1 = __expf(s_[nt][1] - mn0);
            float p2 = __expf(s_[nt][2] - mn1);
            float p3 = __expf(s_[nt][3] - mn1);
            sum0 += p0 + p1;
            sum1 += p2 + p3;
            Ps[pr0 + c]     = f2tf32(p0);
            Ps[pr0 + c + 1] = f2tf32(p1);
            Ps[pr1 + c]     = f2tf32(p2);
            Ps[pr1 + c + 1] = f2tf32(p3);
        }
        sum0 += __shfl_xor_sync(0xffffffffu, sum0, 1);
        sum0 += __shfl_xor_sync(0xffffffffu, sum0, 2);
        sum1 += __shfl_xor_sync(0xffffffffu, sum1, 1);
        sum1 += __shfl_xor_sync(0xffffffffu, sum1, 2);
        l0 = l0 * a0 + sum0;
        l1 = l1 * a1 + sum1;
        m0v = mn0; m1v = mn1;

#pragma unroll
        for (int nt = 0; nt < 8; nt++) {
            acc_o[nt][0] *= a0; acc_o[nt][1] *= a0;
            acc_o[nt][2] *= a1; acc_o[nt][3] *= a1;
        }

        // ---- O += P V  (P rows are warp-private; no sync needed) ----
#pragma unroll
        for (int k = 0; k < 16; k++) {
            uint32_t ap[4];
            ap[0] = Ps[pr0 + 8 * k + qid];
            ap[1] = Ps[pr1 + 8 * k + qid];
            ap[2] = Ps[pr0 + 8 * k + qid + 4];
            ap[3] = Ps[pr1 + 8 * k + qid + 4];
#pragma unroll
            for (int nt = 0; nt < 8; nt++) {
                uint32_t b0 = Vs[(8 * k + qid) * VS_STRIDE + nt * 8 + grp];
                uint32_t b1 = Vs[(8 * k + qid + 4) * VS_STRIDE + nt * 8 + grp];
                mma_tf32(acc_o[nt][0], acc_o[nt][1], acc_o[nt][2], acc_o[nt][3],
                         ap[0], ap[1], ap[2], ap[3], b0, b1);
            }
        }
    }

    // ---- epilogue: normalize, write merged-head layout ----
    const float inv0 = 1.f / l0, inv1 = 1.f / l1;
    const int r0 = qb * 128 + warp * 16 + grp;
#pragma unroll
    for (int nt = 0; nt < 8; nt++) {
        int col = h * HDIM + nt * 8 + 2 * qid;
        float2 o0 = make_float2(acc_o[nt][0] * inv0, acc_o[nt][1] * inv0);
        *reinterpret_cast<float2*>(att + (size_t)(b * SEQ + r0) * DMODEL + col) = o0;
        float2 o1 = make_float2(acc_o[nt][2] * inv1, acc_o[nt][3] * inv1);
        *reinterpret_cast<float2*>(att + (size_t)(b * SEQ + r0 + 8) * DMODEL + col) = o1;
    }
}

// ---------------------------------------------------------------------------
extern "C" void kernel_launch(void* const* d_in, const int* in_sizes, int n_in,
                              void* d_out, int out_size)
{
    const float* x    = (const float*)d_in[0];
    const float* Wqkv = (const float*)d_in[1];
    const float* bqkv = (const float*)d_in[2];
    const float* Wp   = (const float*)d_in[3];
    const float* bp   = (const float*)d_in[4];
    float* out = (float*)d_out;

    float *qkv, *att;
    cudaGetSymbolAddress((void**)&qkv, g_qkv);
    cudaGetSymbolAddress((void**)&att, g_att);

    cudaFuncSetAttribute(fa_kernel,
                         cudaFuncAttributeMaxDynamicSharedMemorySize, FA_SMEM_BYTES);

    // 1) QKV = x @ Wqkv + b
    {
        dim3 grid(QKVN / BN, MROWS / BM);
        sgemm_tf32_bias_kernel<<<grid, 256>>>(x, Wqkv, bqkv, qkv, MROWS, QKVN, DMODEL);
    }
    // 2) fused attention -> att (merged heads)
    {
        dim3 grid(SEQ / 128, BH);
        fa_kernel<<<grid, 256, FA_SMEM_BYTES>>>(qkv, att);
    }
    // 3) out = att @ Wp + bp
    {
        dim3 grid(DMODEL / BN, MROWS / BM);
        sgemm_tf32_bias_kernel<<<grid, 256>>>(att, Wp, bp, out, MROWS, DMODEL, DMODEL);
    }
}

// round 5
// speedup vs baseline: 3.3821x; 1.0529x over previous
#include <cuda_runtime.h>
#include <cuda_bf16.h>
#include <math_constants.h>
#include <cstdint>

#define Bsz 4
#define SEQ 2048
#define DMODEL 1024
#define NHEAD 16
#define HDIM 64
#define BH (Bsz * NHEAD)          // 64
#define MROWS (Bsz * SEQ)         // 8192
#define QKVN (3 * DMODEL)         // 3072

__device__ float g_qkv[MROWS * QKVN];
__device__ float g_att[MROWS * DMODEL];     // tf32-rounded by fa epilogue
__device__ float g_xr[MROWS * DMODEL];      // tf32-rounded x
__device__ float g_wqkv_t[QKVN * DMODEL];   // [3072][1024] K-major, tf32-rounded
__device__ float g_wp_t[DMODEL * DMODEL];   // [1024][1024] K-major, tf32-rounded

// ---------------------------------------------------------------------------
// helpers
// ---------------------------------------------------------------------------
__device__ __forceinline__ uint32_t f2tf32(float x) {
    uint32_t u;
    asm("cvt.rna.tf32.f32 %0, %1;" : "=r"(u) : "f"(x));
    return u;
}

__device__ __forceinline__ void mma_tf32(
    float& d0, float& d1, float& d2, float& d3,
    uint32_t a0, uint32_t a1, uint32_t a2, uint32_t a3,
    uint32_t b0, uint32_t b1)
{
    asm volatile(
        "mma.sync.aligned.m16n8k8.row.col.f32.tf32.tf32.f32 "
        "{%0,%1,%2,%3}, {%4,%5,%6,%7}, {%8,%9}, {%0,%1,%2,%3};\n"
        : "+f"(d0), "+f"(d1), "+f"(d2), "+f"(d3)
        : "r"(a0), "r"(a1), "r"(a2), "r"(a3), "r"(b0), "r"(b1));
}

__device__ __forceinline__ uint32_t smem_u32(const void* p) {
    uint32_t a;
    asm("{ .reg .u64 t; cvta.to.shared.u64 t, %1; cvt.u32.u64 %0, t; }"
        : "=r"(a) : "l"(p));
    return a;
}

__device__ __forceinline__ void cp16(uint32_t dst, const void* src) {
    asm volatile("cp.async.cg.shared.global [%0], [%1], 16;"
                 :: "r"(dst), "l"(src) : "memory");
}
__device__ __forceinline__ void cp_commit() {
    asm volatile("cp.async.commit_group;" ::: "memory");
}
__device__ __forceinline__ void cp_wait1() {
    asm volatile("cp.async.wait_group 1;" ::: "memory");
}

// ---------------------------------------------------------------------------
// pre-round x to tf32 bits
// ---------------------------------------------------------------------------
__global__ __launch_bounds__(256) void round_x_kernel(
    const float* __restrict__ x, float* __restrict__ xr)
{
    size_t i = ((size_t)blockIdx.x * 256 + threadIdx.x) * 4;
    const size_t n = (size_t)MROWS * DMODEL;
    if (i < n) {
        float4 v = *reinterpret_cast<const float4*>(x + i);
        uint4 w;
        w.x = f2tf32(v.x); w.y = f2tf32(v.y);
        w.z = f2tf32(v.z); w.w = f2tf32(v.w);
        *reinterpret_cast<uint4*>(xr + i) = w;
    }
}

// ---------------------------------------------------------------------------
// Weight transpose + tf32 rounding: Wt[n][k] = tf32(W[k][n])
// ---------------------------------------------------------------------------
__global__ __launch_bounds__(256) void transpose_cvt_kernel(
    const float* __restrict__ W, float* __restrict__ Wt, int K, int N)
{
    __shared__ float t[32][33];
    const int kb = blockIdx.x * 32, nb = blockIdx.y * 32;
    const int tx = threadIdx.x, ty = threadIdx.y;   // 32 x 8
#pragma unroll
    for (int i = 0; i < 32; i += 8)
        t[ty + i][tx] = W[(size_t)(kb + ty + i) * N + nb + tx];
    __syncthreads();
#pragma unroll
    for (int i = 0; i < 32; i += 8)
        Wt[(size_t)(nb + ty + i) * K + kb + tx] = __uint_as_float(f2tf32(t[tx][ty + i]));
}

// ---------------------------------------------------------------------------
// tf32 GEMM via mma.sync, big register tiles + cp.async 3-stage pipeline.
// C[M,N] = A[M,K] * Bt[N,K]^T + bias.  A and Bt must be pre-tf32-rounded.
// CTA tile 128(M) x 256(N), BK=16. 8 warps: wm=warp&1 (2) x wn=warp>>1 (4).
// Warp tile 64x64 = mt4 x nt8 of m16n8k8.
// ---------------------------------------------------------------------------
#define GM 128
#define GN 256
#define GK 16
#define ASTR 20                       // row stride (words) for A/B smem tiles
#define A_WORDS (GM * ASTR)           // 2560
#define B_WORDS (GN * ASTR)           // 5120
#define STAGE_WORDS (A_WORDS + B_WORDS)
#define GEMM_SMEM_BYTES (3 * STAGE_WORDS * 4)   // 92160

__global__ __launch_bounds__(256, 1) void tc_gemm_kernel(
    const float* __restrict__ A, const float* __restrict__ Bt,
    const float* __restrict__ bias, float* __restrict__ C,
    int M, int N, int K)
{
    extern __shared__ uint32_t smw[];
    const int tid  = threadIdx.x;
    const int warp = tid >> 5;
    const int lane = tid & 31;
    const int grp  = lane >> 2;
    const int qid  = lane & 3;
    const int wm   = warp & 1;
    const int wn   = warp >> 1;
    const int rowBase = blockIdx.y * GM;
    const int colBase = blockIdx.x * GN;

    const float* Ap = A + (size_t)rowBase * K;
    const float* Bp = Bt + (size_t)colBase * K;
    const uint32_t sbase = smem_u32(smw);

    // staging mapping
    const int sa_r = tid >> 1;             // A: 2 chunks/thread
    const int sa_q = (tid & 1) * 2;        // chunk pair start (we do 2 chunks: q, q+1)
    const int sb_r0 = tid >> 2;            // B: id = tid + i*256 -> r=id>>2, q=id&3
    const int sb_q = tid & 3;

    float acc[4][8][4];
#pragma unroll
    for (int mt = 0; mt < 4; mt++)
#pragma unroll
        for (int nt = 0; nt < 8; nt++)
#pragma unroll
            for (int v = 0; v < 4; v++) acc[mt][nt][v] = 0.f;

    const int nchunk = K / GK;

    auto issue_stage = [&](int c) {
        const int s = c % 3;
        const uint32_t abase = sbase + (s * STAGE_WORDS) * 4;
        const uint32_t bbase = abase + A_WORDS * 4;
        const int k0 = c * GK;
        // A: 128 rows x 4 chunks = 512; thread does ids tid*2, tid*2+1 (same row)
        {
            int id0 = tid * 2;
            int r = id0 >> 2, q = id0 & 3;
            const float* src = Ap + (size_t)r * K + k0 + q * 4;
            cp16(abase + (r * ASTR + q * 4) * 4, src);
            cp16(abase + (r * ASTR + (q + 1) * 4) * 4, src + 4);
        }
        // B: 256 rows x 4 chunks = 1024; ids tid + i*256
#pragma unroll
        for (int i = 0; i < 4; i++) {
            int id = tid + i * 256;
            int r = id >> 2, q = id & 3;
            cp16(bbase + (r * ASTR + q * 4) * 4,
                 Bp + (size_t)r * K + k0 + q * 4);
        }
        cp_commit();
    };

    issue_stage(0);
    issue_stage(1);

    for (int c = 0; c < nchunk; c++) {
        cp_wait1();          // stage c complete (this thread's groups)
        __syncthreads();     // all threads' stage-c parts visible; compute(c-1) done
        if (c + 2 < nchunk) issue_stage(c + 2);
        else cp_commit();    // keep group accounting uniform

        const int s = c % 3;
        const uint32_t* As = smw + s * STAGE_WORDS;
        const uint32_t* Bs = As + A_WORDS;

#pragma unroll
        for (int ks = 0; ks < 16; ks += 8) {
            uint32_t af[4][4];
#pragma unroll
            for (int mt = 0; mt < 4; mt++) {
                const int rb = wm * 64 + mt * 16;
                af[mt][0] = As[(rb + grp) * ASTR + ks + qid];
                af[mt][1] = As[(rb + grp + 8) * ASTR + ks + qid];
                af[mt][2] = As[(rb + grp) * ASTR + ks + qid + 4];
                af[mt][3] = As[(rb + grp + 8) * ASTR + ks + qid + 4];
            }
            uint32_t bf[8][2];
#pragma unroll
            for (int nt = 0; nt < 8; nt++) {
                const int rb = wn * 64 + nt * 8 + grp;
                bf[nt][0] = Bs[rb * ASTR + ks + qid];
                bf[nt][1] = Bs[rb * ASTR + ks + qid + 4];
            }
#pragma unroll
            for (int nt = 0; nt < 8; nt++)
#pragma unroll
                for (int mt = 0; mt < 4; mt++)
                    mma_tf32(acc[mt][nt][0], acc[mt][nt][1],
                             acc[mt][nt][2], acc[mt][nt][3],
                             af[mt][0], af[mt][1], af[mt][2], af[mt][3],
                             bf[nt][0], bf[nt][1]);
        }
    }

    // epilogue
#pragma unroll
    for (int mt = 0; mt < 4; mt++) {
#pragma unroll
        for (int nt = 0; nt < 8; nt++) {
            int c = colBase + wn * 64 + nt * 8 + 2 * qid;
            float bx = bias[c], by = bias[c + 1];
            int r0 = rowBase + wm * 64 + mt * 16 + grp;
            float2 o0 = make_float2(acc[mt][nt][0] + bx, acc[mt][nt][1] + by);
            *reinterpret_cast<float2*>(C + (size_t)r0 * N + c) = o0;
            float2 o1 = make_float2(acc[mt][nt][2] + bx, acc[mt][nt][3] + by);
            *reinterpret_cast<float2*>(C + (size_t)(r0 + 8) * N + c) = o1;
        }
    }
}

// ---------------------------------------------------------------------------
// Fused flash attention (tf32 mma.sync). Epilogue writes tf32-rounded att.
// ---------------------------------------------------------------------------
#define KS_STRIDE 136
#define VS_STRIDE 72
#define PS_STRIDE 132
#define KS_OFF 0
#define VS_OFF (64 * KS_STRIDE)
#define PS_OFF (VS_OFF + 128 * VS_STRIDE)
#define FA_SMEM_WORDS (PS_OFF + 128 * PS_STRIDE)
#define FA_SMEM_BYTES (FA_SMEM_WORDS * 4)

__global__ __launch_bounds__(256) void fa_kernel(
    const float* __restrict__ qkv, float* __restrict__ att)
{
    extern __shared__ uint32_t smw[];
    uint32_t* Ks = smw + KS_OFF;
    uint32_t* Vs = smw + VS_OFF;
    uint32_t* Ps = smw + PS_OFF;

    const int qb = 15 - blockIdx.x;
    const int bh = blockIdx.y;
    const int b = bh >> 4, h = bh & 15;
    const float* Qp = qkv + (size_t)b * SEQ * QKVN + h * HDIM;
    const float* Kp = Qp + DMODEL;
    const float* Vp = Qp + 2 * DMODEL;

    const int tid = threadIdx.x, warp = tid >> 5, lane = tid & 31;
    const int grp = lane >> 2, qid = lane & 3;
    const int la_r = tid >> 1;
    const int la_c = (tid & 1) * 8;

    {
        const float* src = Qp + (size_t)(qb * 128 + la_r) * QKVN + la_c;
#pragma unroll
        for (int k0 = 0; k0 < HDIM; k0 += 16) {
            float4 v0 = *reinterpret_cast<const float4*>(src + k0);
            float4 v1 = *reinterpret_cast<const float4*>(src + k0 + 4);
            Ks[(k0 + la_c + 0) * KS_STRIDE + la_r] = f2tf32(v0.x * 0.125f);
            Ks[(k0 + la_c + 1) * KS_STRIDE + la_r] = f2tf32(v0.y * 0.125f);
            Ks[(k0 + la_c + 2) * KS_STRIDE + la_r] = f2tf32(v0.z * 0.125f);
            Ks[(k0 + la_c + 3) * KS_STRIDE + la_r] = f2tf32(v0.w * 0.125f);
            Ks[(k0 + la_c + 4) * KS_STRIDE + la_r] = f2tf32(v1.x * 0.125f);
            Ks[(k0 + la_c + 5) * KS_STRIDE + la_r] = f2tf32(v1.y * 0.125f);
            Ks[(k0 + la_c + 6) * KS_STRIDE + la_r] = f2tf32(v1.z * 0.125f);
            Ks[(k0 + la_c + 7) * KS_STRIDE + la_r] = f2tf32(v1.w * 0.125f);
        }
    }
    __syncthreads();
    uint32_t aq[8][4];
    {
        const int m0 = warp * 16 + grp;
#pragma unroll
        for (int k = 0; k < 8; k++) {
            aq[k][0] = Ks[(8 * k + qid) * KS_STRIDE + m0];
            aq[k][1] = Ks[(8 * k + qid) * KS_STRIDE + m0 + 8];
            aq[k][2] = Ks[(8 * k + qid + 4) * KS_STRIDE + m0];
            aq[k][3] = Ks[(8 * k + qid + 4) * KS_STRIDE + m0 + 8];
        }
    }

    float m0v = -CUDART_INF_F, m1v = -CUDART_INF_F;
    float l0 = 0.f, l1 = 0.f;
    float acc_o[8][4];
#pragma unroll
    for (int j = 0; j < 8; j++)
#pragma unroll
        for (int v = 0; v < 4; v++) acc_o[j][v] = 0.f;

    for (int kb = 0; kb <= qb; kb++) {
        __syncthreads();
        {
            const float* src = Kp + (size_t)(kb * 128 + la_r) * QKVN + la_c;
#pragma unroll
            for (int k0 = 0; k0 < HDIM; k0 += 16) {
                float4 v0 = *reinterpret_cast<const float4*>(src + k0);
                float4 v1 = *reinterpret_cast<const float4*>(src + k0 + 4);
                Ks[(k0 + la_c + 0) * KS_STRIDE + la_r] = f2tf32(v0.x);
                Ks[(k0 + la_c + 1) * KS_STRIDE + la_r] = f2tf32(v0.y);
                Ks[(k0 + la_c + 2) * KS_STRIDE + la_r] = f2tf32(v0.z);
                Ks[(k0 + la_c + 3) * KS_STRIDE + la_r] = f2tf32(v0.w);
                Ks[(k0 + la_c + 4) * KS_STRIDE + la_r] = f2tf32(v1.x);
                Ks[(k0 + la_c + 5) * KS_STRIDE + la_r] = f2tf32(v1.y);
                Ks[(k0 + la_c + 6) * KS_STRIDE + la_r] = f2tf32(v1.z);
                Ks[(k0 + la_c + 7) * KS_STRIDE + la_r] = f2tf32(v1.w);
            }
        }
        {
#pragma unroll
            for (int rep = 0; rep < 8; rep++) {
                int unit = tid + rep * 256;
                int row = unit >> 4;
                int f4  = unit & 15;
                float4 v = *reinterpret_cast<const float4*>(
                    Vp + (size_t)(kb * 128 + row) * QKVN + 4 * f4);
                Vs[row * VS_STRIDE + 4 * f4 + 0] = f2tf32(v.x);
                Vs[row * VS_STRIDE + 4 * f4 + 1] = f2tf32(v.y);
                Vs[row * VS_STRIDE + 4 * f4 + 2] = f2tf32(v.z);
                Vs[row * VS_STRIDE + 4 * f4 + 3] = f2tf32(v.w);
            }
        }
        __syncthreads();

        float s_[16][4];
#pragma unroll
        for (int nt = 0; nt < 16; nt++)
#pragma unroll
            for (int v = 0; v < 4; v++) s_[nt][v] = 0.f;
#pragma unroll
        for (int k = 0; k < 8; k++) {
#pragma unroll
            for (int nt = 0; nt < 16; nt++) {
                uint32_t b0 = Ks[(8 * k + qid) * KS_STRIDE + nt * 8 + grp];
                uint32_t b1 = Ks[(8 * k + qid + 4) * KS_STRIDE + nt * 8 + grp];
                mma_tf32(s_[nt][0], s_[nt][1], s_[nt][2], s_[nt][3],
                         aq[k][0], aq[k][1], aq[k][2], aq[k][3], b0, b1);
            }
        }

        if (kb == qb) {
            const int r0 = warp * 16 + grp, r1 = r0 + 8;
#pragma unroll
            for (int nt = 0; nt < 16; nt++) {
                int c = nt * 8 + 2 * qid;
                if (c > r0)     s_[nt][0] = -CUDART_INF_F;
                if (c + 1 > r0) s_[nt][1] = -CUDART_INF_F;
                if (c > r1)     s_[nt][2] = -CUDART_INF_F;
                if (c + 1 > r1) s_[nt][3] = -CUDART_INF_F;
            }
        }

        float mx0 = -CUDART_INF_F, mx1 = -CUDART_INF_F;
#pragma unroll
        for (int nt = 0; nt < 16; nt++) {
            mx0 = fmaxf(mx0, fmaxf(s_[nt][0], s_[nt][1]));
            mx1 = fmaxf(mx1, fmaxf(s_[nt][2], s_[nt][3]));
        }
        mx0 = fmaxf(mx0, __shfl_xor_sync(0xffffffffu, mx0, 1));
        mx0 = fmaxf(mx0, __shfl_xor_sync(0xffffffffu, mx0, 2));
        mx1 = fmaxf(mx1, __shfl_xor_sync(0xffffffffu, mx1, 1));
        mx1 = fmaxf(mx1, __shfl_xor_sync(0xffffffffu, mx1, 2));

        float mn0 = fmaxf(m0v, mx0), mn1 = fmaxf(m1v, mx1);
        float a0 = __expf(m0v - mn0), a1 = __expf(m1v - mn1);

        const int pr0 = (warp * 16 + grp) * PS_STRIDE;
        const int pr1 = pr0 + 8 * PS_STRIDE;
        float sum0 = 0.f, sum1 = 0.f;
#pragma unroll
        for (int nt = 0; nt < 16; nt++) {
            int c = nt * 8 + 2 * qid;
            float p0 = __expf(s_[nt][0] - mn0);
            float p1 = __expf(s_[nt][1] - mn0);
            float p2 = __expf(s_[nt][2] - mn1);
            float p3 = __expf(s_[nt][3] - mn1);
            sum0 += p0 + p1;
            sum1 += p2 + p3;
            Ps[pr0 + c]     = f2tf32(p0);
            Ps[pr0 + c + 1] = f2tf32(p1);
            Ps[pr1 + c]     = f2tf32(p2);
            Ps[pr1 + c + 1] = f2tf32(p3);
        }
        sum0 += __shfl_xor_sync(0xffffffffu, sum0, 1);
        sum0 += __shfl_xor_sync(0xffffffffu, sum0, 2);
        sum1 += __shfl_xor_sync(0xffffffffu, sum1, 1);
        sum1 += __shfl_xor_sync(0xffffffffu, sum1, 2);
        l0 = l0 * a0 + sum0;
        l1 = l1 * a1 + sum1;
        m0v = mn0; m1v = mn1;

#pragma unroll
        for (int nt = 0; nt < 8; nt++) {
            acc_o[nt][0] *= a0; acc_o[nt][1] *= a0;
            acc_o[nt][2] *= a1; acc_o[nt][3] *= a1;
        }

#pragma unroll
        for (int k = 0; k < 16; k++) {
            uint32_t ap[4];
            ap[0] = Ps[pr0 + 8 * k + qid];
            ap[1] = Ps[pr1 + 8 * k + qid];
            ap[2] = Ps[pr0 + 8 * k + qid + 4];
            ap[3] = Ps[pr1 + 8 * k + qid + 4];
#pragma unroll
            for (int nt = 0; nt < 8; nt++) {
                uint32_t b0 = Vs[(8 * k + qid) * VS_STRIDE + nt * 8 + grp];
                uint32_t b1 = Vs[(8 * k + qid + 4) * VS_STRIDE + nt * 8 + grp];
                mma_tf32(acc_o[nt][0], acc_o[nt][1], acc_o[nt][2], acc_o[nt][3],
                         ap[0], ap[1], ap[2], ap[3], b0, b1);
            }
        }
    }

    // epilogue: normalize + tf32-round (att feeds the tf32 proj GEMM)
    const float inv0 = 1.f / l0, inv1 = 1.f / l1;
    const int r0 = qb * 128 + warp * 16 + grp;
#pragma unroll
    for (int nt = 0; nt < 8; nt++) {
        int col = h * HDIM + nt * 8 + 2 * qid;
        uint2 o0, o1;
        o0.x = f2tf32(acc_o[nt][0] * inv0);
        o0.y = f2tf32(acc_o[nt][1] * inv0);
        *reinterpret_cast<uint2*>(att + (size_t)(b * SEQ + r0) * DMODEL + col) = o0;
        o1.x = f2tf32(acc_o[nt][2] * inv1);
        o1.y = f2tf32(acc_o[nt][3] * inv1);
        *reinterpret_cast<uint2*>(att + (size_t)(b * SEQ + r0 + 8) * DMODEL + col) = o1;
    }
}

// ---------------------------------------------------------------------------
extern "C" void kernel_launch(void* const* d_in, const int* in_sizes, int n_in,
                              void* d_out, int out_size)
{
    const float* x    = (const float*)d_in[0];
    const float* Wqkv = (const float*)d_in[1];
    const float* bqkv = (const float*)d_in[2];
    const float* Wp   = (const float*)d_in[3];
    const float* bp   = (const float*)d_in[4];
    float* out = (float*)d_out;

    float *qkv, *att, *xr, *wqkv_t, *wp_t;
    cudaGetSymbolAddress((void**)&qkv, g_qkv);
    cudaGetSymbolAddress((void**)&att, g_att);
    cudaGetSymbolAddress((void**)&xr, g_xr);
    cudaGetSymbolAddress((void**)&wqkv_t, g_wqkv_t);
    cudaGetSymbolAddress((void**)&wp_t, g_wp_t);

    cudaFuncSetAttribute(fa_kernel,
                         cudaFuncAttributeMaxDynamicSharedMemorySize, FA_SMEM_BYTES);
    cudaFuncSetAttribute(tc_gemm_kernel,
                         cudaFuncAttributeMaxDynamicSharedMemorySize, GEMM_SMEM_BYTES);

    // 0) precondition operands (tf32-round; transpose weights to K-major)
    {
        round_x_kernel<<<(MROWS * DMODEL / 4 + 255) / 256, 256>>>(x, xr);
        dim3 blk(32, 8);
        transpose_cvt_kernel<<<dim3(DMODEL / 32, QKVN / 32), blk>>>(Wqkv, wqkv_t, DMODEL, QKVN);
        transpose_cvt_kernel<<<dim3(DMODEL / 32, DMODEL / 32), blk>>>(Wp, wp_t, DMODEL, DMODEL);
    }
    // 1) QKV = x @ Wqkv + b
    {
        dim3 grid(QKVN / GN, MROWS / GM);
        tc_gemm_kernel<<<grid, 256, GEMM_SMEM_BYTES>>>(xr, wqkv_t, bqkv, qkv,
                                                       MROWS, QKVN, DMODEL);
    }
    // 2) fused attention -> att (tf32-rounded)
    {
        dim3 grid(SEQ / 128, BH);
        fa_kernel<<<grid, 256, FA_SMEM_BYTES>>>(qkv, att);
    }
    // 3) out = att @ Wp + bp
    {
        dim3 grid(DMODEL / GN, MROWS / GM);
        tc_gemm_kernel<<<grid, 256, GEMM_SMEM_BYTES>>>(att, wp_t, bp, out,
                                                       MROWS, DMODEL, DMODEL);
    }
}

// round 6
// speedup vs baseline: 5.6675x; 1.6758x over previous
#include <cuda_runtime.h>
#include <cuda_fp16.h>
#include <math_constants.h>
#include <cstdint>

#define Bsz 4
#define SEQ 2048
#define DMODEL 1024
#define NHEAD 16
#define HDIM 64
#define BH (Bsz * NHEAD)          // 64
#define MROWS (Bsz * SEQ)         // 8192
#define QKVN (3 * DMODEL)         // 3072

__device__ __half g_qkv[MROWS * QKVN];
__device__ __half g_att[MROWS * DMODEL];
__device__ __half g_xh[MROWS * DMODEL];
__device__ __half g_wqkv_t[QKVN * DMODEL];   // [3072][1024] K-major
__device__ __half g_wp_t[DMODEL * DMODEL];   // [1024][1024] K-major

// ---------------------------------------------------------------------------
__device__ __forceinline__ void mma_f16(
    float& d0, float& d1, float& d2, float& d3,
    uint32_t a0, uint32_t a1, uint32_t a2, uint32_t a3,
    uint32_t b0, uint32_t b1)
{
    asm volatile(
        "mma.sync.aligned.m16n8k16.row.col.f32.f16.f16.f32 "
        "{%0,%1,%2,%3}, {%4,%5,%6,%7}, {%8,%9}, {%0,%1,%2,%3};\n"
        : "+f"(d0), "+f"(d1), "+f"(d2), "+f"(d3)
        : "r"(a0), "r"(a1), "r"(a2), "r"(a3), "r"(b0), "r"(b1));
}

__device__ __forceinline__ void cp16(uint32_t dst, const void* src) {
    asm volatile("cp.async.cg.shared.global [%0], [%1], 16;"
                 :: "r"(dst), "l"(src) : "memory");
}
__device__ __forceinline__ void cp_commit() {
    asm volatile("cp.async.commit_group;" ::: "memory");
}
__device__ __forceinline__ void cp_wait1() {
    asm volatile("cp.async.wait_group 1;" ::: "memory");
}
__device__ __forceinline__ uint32_t smem_u32(const void* p) {
    uint32_t a;
    asm("{ .reg .u64 t; cvta.to.shared.u64 t, %1; cvt.u32.u64 %0, t; }"
        : "=r"(a) : "l"(p));
    return a;
}

// ---------------------------------------------------------------------------
// prepass: fp32 -> fp16 conversions
// ---------------------------------------------------------------------------
__global__ __launch_bounds__(256) void x2h_kernel(
    const float* __restrict__ x, __half* __restrict__ xh)
{
    size_t i = ((size_t)blockIdx.x * 256 + threadIdx.x) * 4;
    if (i < (size_t)MROWS * DMODEL) {
        float4 v = *reinterpret_cast<const float4*>(x + i);
        __half2 h0 = __floats2half2_rn(v.x, v.y);
        __half2 h1 = __floats2half2_rn(v.z, v.w);
        *reinterpret_cast<uint2*>(xh + i) =
            make_uint2(*(uint32_t*)&h0, *(uint32_t*)&h1);
    }
}

__global__ __launch_bounds__(256) void transpose_h_kernel(
    const float* __restrict__ W, __half* __restrict__ Wt, int K, int N)
{
    __shared__ float t[32][33];
    const int kb = blockIdx.x * 32, nb = blockIdx.y * 32;
    const int tx = threadIdx.x, ty = threadIdx.y;   // 32 x 8
#pragma unroll
    for (int i = 0; i < 32; i += 8)
        t[ty + i][tx] = W[(size_t)(kb + ty + i) * N + nb + tx];
    __syncthreads();
#pragma unroll
    for (int i = 0; i < 32; i += 8)
        Wt[(size_t)(nb + ty + i) * K + kb + tx] = __float2half_rn(t[tx][ty + i]);
}

// ---------------------------------------------------------------------------
// fp16 GEMM via mma.sync m16n8k16 + cp.async 3-stage pipeline.
// C[M,N] = A[M,K] * Bt[N,K]^T + bias.  CTA tile 128x256, BK=32 halves.
// 8 warps: wm=warp&1 x wn=warp>>1; warp tile 64x64 (mt4 x nt8).
// ---------------------------------------------------------------------------
#define GM 128
#define GN 256
#define GKH 32                         // K halves per chunk
#define ASTR_H 40                      // halves per A/B smem row (16B aligned, conflict-free)
#define A_HALF (GM * ASTR_H)           // 5120
#define B_HALF (GN * ASTR_H)           // 10240
#define STAGE_HALF (A_HALF + B_HALF)   // 15360
#define STAGE_WORDS (STAGE_HALF / 2)   // 7680
#define A_WORDS (A_HALF / 2)           // 2560
#define GEMM_SMEM_BYTES (3 * STAGE_HALF * 2)   // 92160

template <int HALF_OUT>
__global__ __launch_bounds__(256, 1) void gemm_f16_kernel(
    const __half* __restrict__ A, const __half* __restrict__ Bt,
    const float* __restrict__ bias, void* __restrict__ Cv,
    int M, int N, int K)
{
    extern __shared__ uint32_t smw[];
    const int tid  = threadIdx.x;
    const int warp = tid >> 5;
    const int lane = tid & 31;
    const int grp  = lane >> 2;
    const int qid  = lane & 3;
    const int wm   = warp & 1;
    const int wn   = warp >> 1;
    const int rowBase = blockIdx.y * GM;
    const int colBase = blockIdx.x * GN;

    const __half* Ap = A + (size_t)rowBase * K;
    const __half* Bp = Bt + (size_t)colBase * K;
    const uint32_t sbase = smem_u32(smw);

    float acc[4][8][4];
#pragma unroll
    for (int mt = 0; mt < 4; mt++)
#pragma unroll
        for (int nt = 0; nt < 8; nt++)
#pragma unroll
            for (int v = 0; v < 4; v++) acc[mt][nt][v] = 0.f;

    const int nchunk = K / GKH;

    auto issue_stage = [&](int c) {
        const int s = c % 3;
        const uint32_t abase = sbase + s * STAGE_HALF * 2;
        const uint32_t bbase = abase + A_HALF * 2;
        const int k0 = c * GKH;
        // A: 128 rows x 4 x 16B chunks = 512 cp16; thread does 2 (same row)
        {
            int id0 = tid * 2;
            int r = id0 >> 2, q = id0 & 3;      // q in {0,2}
            const __half* src = Ap + (size_t)r * K + k0 + q * 8;
            cp16(abase + r * (ASTR_H * 2) + q * 16, src);
            cp16(abase + r * (ASTR_H * 2) + (q + 1) * 16, src + 8);
        }
        // B: 256 rows x 4 chunks = 1024 cp16; 4 per thread
#pragma unroll
        for (int i = 0; i < 4; i++) {
            int id = tid + i * 256;
            int r = id >> 2, q = id & 3;
            cp16(bbase + r * (ASTR_H * 2) + q * 16,
                 Bp + (size_t)r * K + k0 + q * 8);
        }
        cp_commit();
    };

    issue_stage(0);
    issue_stage(1);

    for (int c = 0; c < nchunk; c++) {
        cp_wait1();
        __syncthreads();
        if (c + 2 < nchunk) issue_stage(c + 2);
        else cp_commit();

        const uint32_t* As = smw + (c % 3) * STAGE_WORDS;
        const uint32_t* Bs = As + A_WORDS;

#pragma unroll
        for (int s = 0; s < 2; s++) {          // two k16 steps per 32-half chunk
            const int kw = s * 8;              // word offset
            uint32_t af[4][4];
#pragma unroll
            for (int mt = 0; mt < 4; mt++) {
                const int rb = wm * 64 + mt * 16;
                af[mt][0] = As[(rb + grp) * 20 + kw + qid];
                af[mt][1] = As[(rb + grp + 8) * 20 + kw + qid];
                af[mt][2] = As[(rb + grp) * 20 + kw + qid + 4];
                af[mt][3] = As[(rb + grp + 8) * 20 + kw + qid + 4];
            }
            uint32_t bf[8][2];
#pragma unroll
            for (int nt = 0; nt < 8; nt++) {
                const int rb = wn * 64 + nt * 8 + grp;
                bf[nt][0] = Bs[rb * 20 + kw + qid];
                bf[nt][1] = Bs[rb * 20 + kw + qid + 4];
            }
#pragma unroll
            for (int nt = 0; nt < 8; nt++)
#pragma unroll
                for (int mt = 0; mt < 4; mt++)
                    mma_f16(acc[mt][nt][0], acc[mt][nt][1],
                            acc[mt][nt][2], acc[mt][nt][3],
                            af[mt][0], af[mt][1], af[mt][2], af[mt][3],
                            bf[nt][0], bf[nt][1]);
        }
    }

#pragma unroll
    for (int mt = 0; mt < 4; mt++) {
#pragma unroll
        for (int nt = 0; nt < 8; nt++) {
            int c = colBase + wn * 64 + nt * 8 + 2 * qid;
            float bx = bias[c], by = bias[c + 1];
            int r0 = rowBase + wm * 64 + mt * 16 + grp;
            if (HALF_OUT) {
                __half* C = (__half*)Cv;
                __half2 o0 = __floats2half2_rn(acc[mt][nt][0] + bx, acc[mt][nt][1] + by);
                *reinterpret_cast<__half2*>(C + (size_t)r0 * N + c) = o0;
                __half2 o1 = __floats2half2_rn(acc[mt][nt][2] + bx, acc[mt][nt][3] + by);
                *reinterpret_cast<__half2*>(C + (size_t)(r0 + 8) * N + c) = o1;
            } else {
                float* C = (float*)Cv;
                float2 o0 = make_float2(acc[mt][nt][0] + bx, acc[mt][nt][1] + by);
                *reinterpret_cast<float2*>(C + (size_t)r0 * N + c) = o0;
                float2 o1 = make_float2(acc[mt][nt][2] + bx, acc[mt][nt][3] + by);
                *reinterpret_cast<float2*>(C + (size_t)(r0 + 8) * N + c) = o1;
            }
        }
    }
}

// ---------------------------------------------------------------------------
// Fused flash attention, fp16 mma m16n8k16.
// One CTA = (b,h) x 128 q-rows; 8 warps x 16 rows.
// smem halves: Ks[128][88] | Vs[64][136] (V transposed) | Ps[128][136]
// ---------------------------------------------------------------------------
#define KS_W 44                               // words per Ks row (88 halves)
#define VS_W 68                               // words per Vs row (136 halves)
#define PS_W 68
#define KS_OFFW 0
#define VS_OFFW (128 * KS_W)                  // 5632
#define PS_OFFW (VS_OFFW + 64 * VS_W)         // 9984
#define FA_SMEM_WORDS (PS_OFFW + 128 * PS_W)  // 18688
#define FA_SMEM_BYTES (FA_SMEM_WORDS * 4)     // 74752

__global__ __launch_bounds__(256) void fa_kernel(
    const __half* __restrict__ qkv, __half* __restrict__ att)
{
    extern __shared__ uint32_t smw[];
    uint32_t* Ks = smw + KS_OFFW;
    uint32_t* Vs = smw + VS_OFFW;
    uint32_t* Ps = smw + PS_OFFW;
    __half*  Vsh = reinterpret_cast<__half*>(Vs);

    const int qb = 15 - blockIdx.x;
    const int bh = blockIdx.y;
    const int b = bh >> 4, h = bh & 15;
    const __half* Qp = qkv + (size_t)b * SEQ * QKVN + h * HDIM;
    const __half* Kp = Qp + DMODEL;
    const __half* Vp = Qp + 2 * DMODEL;

    const int tid = threadIdx.x, warp = tid >> 5, lane = tid & 31;
    const int grp = lane >> 2, qid = lane & 3;

    // ---- stage Q (scaled 0.125) into Ks rows ----
    {
        const __half2 sc = __floats2half2_rn(0.125f, 0.125f);
#pragma unroll
        for (int i = 0; i < 4; i++) {
            int id = tid + i * 256;
            int r = id >> 3, u = id & 7;               // row, 8-half group
            uint2 v = *reinterpret_cast<const uint2*>(
                Qp + (size_t)(qb * 128 + r) * QKVN + u * 8 + 0);
            uint2 w = *reinterpret_cast<const uint2*>(
                Qp + (size_t)(qb * 128 + r) * QKVN + u * 8 + 4);
            __half2 h0 = __hmul2(*(__half2*)&v.x, sc);
            __half2 h1 = __hmul2(*(__half2*)&v.y, sc);
            __half2 h2 = __hmul2(*(__half2*)&w.x, sc);
            __half2 h3 = __hmul2(*(__half2*)&w.y, sc);
            uint32_t* dst = Ks + r * KS_W + u * 4;
            dst[0] = *(uint32_t*)&h0; dst[1] = *(uint32_t*)&h1;
            dst[2] = *(uint32_t*)&h2; dst[3] = *(uint32_t*)&h3;
        }
    }
    __syncthreads();

    // ---- pull Q A-fragments (4 k16 steps over d=64) ----
    uint32_t aq[4][4];
    {
        const int m0 = warp * 16 + grp;
#pragma unroll
        for (int s = 0; s < 4; s++) {
            aq[s][0] = Ks[m0 * KS_W + s * 8 + qid];
            aq[s][1] = Ks[(m0 + 8) * KS_W + s * 8 + qid];
            aq[s][2] = Ks[m0 * KS_W + s * 8 + qid + 4];
            aq[s][3] = Ks[(m0 + 8) * KS_W + s * 8 + qid + 4];
        }
    }

    float m0v = -CUDART_INF_F, m1v = -CUDART_INF_F;
    float l0 = 0.f, l1 = 0.f;
    float acc_o[8][4];
#pragma unroll
    for (int j = 0; j < 8; j++)
#pragma unroll
        for (int v = 0; v < 4; v++) acc_o[j][v] = 0.f;

    for (int kb = 0; kb <= qb; kb++) {
        __syncthreads();
        // ---- stage K rows ----
#pragma unroll
        for (int i = 0; i < 4; i++) {
            int id = tid + i * 256;
            int r = id >> 3, u = id & 7;
            uint4 v = *reinterpret_cast<const uint4*>(
                Kp + (size_t)(kb * 128 + r) * QKVN + u * 8);
            uint32_t* dst = Ks + r * KS_W + u * 4;
            dst[0] = v.x; dst[1] = v.y; dst[2] = v.z; dst[3] = v.w;
        }
        // ---- stage V transposed: Vs[d][k] = V[k][d] ----
#pragma unroll
        for (int i = 0; i < 8; i++) {
            int id = tid + i * 256;
            int k = id >> 4, dg = id & 15;
            uint2 v = *reinterpret_cast<const uint2*>(
                Vp + (size_t)(kb * 128 + k) * QKVN + dg * 4);
            __half2 p0 = *(__half2*)&v.x;
            __half2 p1 = *(__half2*)&v.y;
            Vsh[(dg * 4 + 0) * (VS_W * 2) + k] = __low2half(p0);
            Vsh[(dg * 4 + 1) * (VS_W * 2) + k] = __high2half(p0);
            Vsh[(dg * 4 + 2) * (VS_W * 2) + k] = __low2half(p1);
            Vsh[(dg * 4 + 3) * (VS_W * 2) + k] = __high2half(p1);
        }
        __syncthreads();

        // ---- S = Q K^T ----
        float s_[16][4];
#pragma unroll
        for (int nt = 0; nt < 16; nt++)
#pragma unroll
            for (int v = 0; v < 4; v++) s_[nt][v] = 0.f;
#pragma unroll
        for (int s = 0; s < 4; s++) {
#pragma unroll
            for (int nt = 0; nt < 16; nt++) {
                const int n = nt * 8 + grp;
                uint32_t b0 = Ks[n * KS_W + s * 8 + qid];
                uint32_t b1 = Ks[n * KS_W + s * 8 + qid + 4];
                mma_f16(s_[nt][0], s_[nt][1], s_[nt][2], s_[nt][3],
                        aq[s][0], aq[s][1], aq[s][2], aq[s][3], b0, b1);
            }
        }

        if (kb == qb) {
            const int r0 = warp * 16 + grp, r1 = r0 + 8;
#pragma unroll
            for (int nt = 0; nt < 16; nt++) {
                int c = nt * 8 + 2 * qid;
                if (c > r0)     s_[nt][0] = -CUDART_INF_F;
                if (c + 1 > r0) s_[nt][1] = -CUDART_INF_F;
                if (c > r1)     s_[nt][2] = -CUDART_INF_F;
                if (c + 1 > r1) s_[nt][3] = -CUDART_INF_F;
            }
        }

        // ---- online softmax ----
        float mx0 = -CUDART_INF_F, mx1 = -CUDART_INF_F;
#pragma unroll
        for (int nt = 0; nt < 16; nt++) {
            mx0 = fmaxf(mx0, fmaxf(s_[nt][0], s_[nt][1]));
            mx1 = fmaxf(mx1, fmaxf(s_[nt][2], s_[nt][3]));
        }
        mx0 = fmaxf(mx0, __shfl_xor_sync(0xffffffffu, mx0, 1));
        mx0 = fmaxf(mx0, __shfl_xor_sync(0xffffffffu, mx0, 2));
        mx1 = fmaxf(mx1, __shfl_xor_sync(0xffffffffu, mx1, 1));
        mx1 = fmaxf(mx1, __shfl_xor_sync(0xffffffffu, mx1, 2));

        float mn0 = fmaxf(m0v, mx0), mn1 = fmaxf(m1v, mx1);
        float a0 = __expf(m0v - mn0), a1 = __expf(m1v - mn1);

        const int pr0 = (warp * 16 + grp) * PS_W;
        const int pr1 = pr0 + 8 * PS_W;
        float sum0 = 0.f, sum1 = 0.f;
#pragma unroll
        for (int nt = 0; nt < 16; nt++) {
            float p0 = __expf(s_[nt][0] - mn0);
            float p1 = __expf(s_[nt][1] - mn0);
            float p2 = __expf(s_[nt][2] - mn1);
            float p3 = __expf(s_[nt][3] - mn1);
            sum0 += p0 + p1;
            sum1 += p2 + p3;
            __half2 q0 = __floats2half2_rn(p0, p1);
            __half2 q1 = __floats2half2_rn(p2, p3);
            Ps[pr0 + nt * 4 + qid] = *(uint32_t*)&q0;
            Ps[pr1 + nt * 4 + qid] = *(uint32_t*)&q1;
        }
        sum0 += __shfl_xor_sync(0xffffffffu, sum0, 1);
        sum0 += __shfl_xor_sync(0xffffffffu, sum0, 2);
        sum1 += __shfl_xor_sync(0xffffffffu, sum1, 1);
        sum1 += __shfl_xor_sync(0xffffffffu, sum1, 2);
        l0 = l0 * a0 + sum0;
        l1 = l1 * a1 + sum1;
        m0v = mn0; m1v = mn1;

#pragma unroll
        for (int nt = 0; nt < 8; nt++) {
            acc_o[nt][0] *= a0; acc_o[nt][1] *= a0;
            acc_o[nt][2] *= a1; acc_o[nt][3] *= a1;
        }

        // ---- O += P V (P rows warp-private) ----
        const int m0r = (warp * 16 + grp) * PS_W;
#pragma unroll
        for (int s = 0; s < 8; s++) {          // 128 k halves = 8 k16 steps
            uint32_t ap[4];
            ap[0] = Ps[m0r + s * 8 + qid];
            ap[1] = Ps[m0r + 8 * PS_W + s * 8 + qid];
            ap[2] = Ps[m0r + s * 8 + qid + 4];
            ap[3] = Ps[m0r + 8 * PS_W + s * 8 + qid + 4];
#pragma unroll
            for (int nt = 0; nt < 8; nt++) {
                const int n = nt * 8 + grp;
                uint32_t b0 = Vs[n * VS_W + s * 8 + qid];
                uint32_t b1 = Vs[n * VS_W + s * 8 + qid + 4];
                mma_f16(acc_o[nt][0], acc_o[nt][1], acc_o[nt][2], acc_o[nt][3],
                        ap[0], ap[1], ap[2], ap[3], b0, b1);
            }
        }
    }

    // ---- epilogue ----
    const float inv0 = 1.f / l0, inv1 = 1.f / l1;
    const int r0 = qb * 128 + warp * 16 + grp;
#pragma unroll
    for (int nt = 0; nt < 8; nt++) {
        int col = h * HDIM + nt * 8 + 2 * qid;
        __half2 o0 = __floats2half2_rn(acc_o[nt][0] * inv0, acc_o[nt][1] * inv0);
        *reinterpret_cast<__half2*>(att + (size_t)(b * SEQ + r0) * DMODEL + col) = o0;
        __half2 o1 = __floats2half2_rn(acc_o[nt][2] * inv1, acc_o[nt][3] * inv1);
        *reinterpret_cast<__half2*>(att + (size_t)(b * SEQ + r0 + 8) * DMODEL + col) = o1;
    }
}

// ---------------------------------------------------------------------------
extern "C" void kernel_launch(void* const* d_in, const int* in_sizes, int n_in,
                              void* d_out, int out_size)
{
    const float* x    = (const float*)d_in[0];
    const float* Wqkv = (const float*)d_in[1];
    const float* bqkv = (const float*)d_in[2];
    const float* Wp   = (const float*)d_in[3];
    const float* bp   = (const float*)d_in[4];
    float* out = (float*)d_out;

    __half *qkv, *att, *xh, *wqkv_t, *wp_t;
    cudaGetSymbolAddress((void**)&qkv, g_qkv);
    cudaGetSymbolAddress((void**)&att, g_att);
    cudaGetSymbolAddress((void**)&xh, g_xh);
    cudaGetSymbolAddress((void**)&wqkv_t, g_wqkv_t);
    cudaGetSymbolAddress((void**)&wp_t, g_wp_t);

    cudaFuncSetAttribute(fa_kernel,
                         cudaFuncAttributeMaxDynamicSharedMemorySize, FA_SMEM_BYTES);
    cudaFuncSetAttribute(gemm_f16_kernel<1>,
                         cudaFuncAttributeMaxDynamicSharedMemorySize, GEMM_SMEM_BYTES);
    cudaFuncSetAttribute(gemm_f16_kernel<0>,
                         cudaFuncAttributeMaxDynamicSharedMemorySize, GEMM_SMEM_BYTES);

    // 0) convert inputs to fp16
    x2h_kernel<<<(MROWS * DMODEL / 4 + 255) / 256, 256>>>(x, xh);
    {
        dim3 blk(32, 8);
        transpose_h_kernel<<<dim3(DMODEL / 32, QKVN / 32), blk>>>(Wqkv, wqkv_t, DMODEL, QKVN);
        transpose_h_kernel<<<dim3(DMODEL / 32, DMODEL / 32), blk>>>(Wp, wp_t, DMODEL, DMODEL);
    }
    // 1) QKV = x @ Wqkv + b  (half out)
    {
        dim3 grid(QKVN / GN, MROWS / GM);
        gemm_f16_kernel<1><<<grid, 256, GEMM_SMEM_BYTES>>>(xh, wqkv_t, bqkv, qkv,
                                                           MROWS, QKVN, DMODEL);
    }
    // 2) fused attention -> att (half)
    {
        dim3 grid(SEQ / 128, BH);
        fa_kernel<<<grid, 256, FA_SMEM_BYTES>>>(qkv, att);
    }
    // 3) out = att @ Wp + bp  (float out)
    {
        dim3 grid(DMODEL / GN, MROWS / GM);
        gemm_f16_kernel<0><<<grid, 256, GEMM_SMEM_BYTES>>>(att, wp_t, bp, out,
                                                           MROWS, DMODEL, DMODEL);
    }
}

// round 7
// speedup vs baseline: 5.7778x; 1.0195x over previous
#include <cuda_runtime.h>
#include <cuda_fp16.h>
#include <math_constants.h>
#include <cstdint>

#define Bsz 4
#define SEQ 2048
#define DMODEL 1024
#define NHEAD 16
#define HDIM 64
#define BH (Bsz * NHEAD)          // 64
#define MROWS (Bsz * SEQ)         // 8192
#define QKVN (3 * DMODEL)         // 3072

__device__ __half g_qkv[MROWS * QKVN];
__device__ __half g_att[MROWS * DMODEL];
__device__ __half g_xh[MROWS * DMODEL];
__device__ __half g_wqkv_t[QKVN * DMODEL];   // [3072][1024] K-major
__device__ __half g_wp_t[DMODEL * DMODEL];   // [1024][1024] K-major

// ---------------------------------------------------------------------------
__device__ __forceinline__ void mma_f16(
    float& d0, float& d1, float& d2, float& d3,
    uint32_t a0, uint32_t a1, uint32_t a2, uint32_t a3,
    uint32_t b0, uint32_t b1)
{
    asm volatile(
        "mma.sync.aligned.m16n8k16.row.col.f32.f16.f16.f32 "
        "{%0,%1,%2,%3}, {%4,%5,%6,%7}, {%8,%9}, {%0,%1,%2,%3};\n"
        : "+f"(d0), "+f"(d1), "+f"(d2), "+f"(d3)
        : "r"(a0), "r"(a1), "r"(a2), "r"(a3), "r"(b0), "r"(b1));
}

__device__ __forceinline__ void ldm_x4(
    uint32_t& r0, uint32_t& r1, uint32_t& r2, uint32_t& r3, uint32_t addr)
{
    asm volatile("ldmatrix.sync.aligned.m8n8.x4.shared.b16 {%0,%1,%2,%3}, [%4];"
        : "=r"(r0), "=r"(r1), "=r"(r2), "=r"(r3) : "r"(addr));
}

__device__ __forceinline__ void cp16(uint32_t dst, const void* src) {
    asm volatile("cp.async.cg.shared.global [%0], [%1], 16;"
                 :: "r"(dst), "l"(src) : "memory");
}
__device__ __forceinline__ void cp_commit() {
    asm volatile("cp.async.commit_group;" ::: "memory");
}
__device__ __forceinline__ void cp_wait1() {
    asm volatile("cp.async.wait_group 1;" ::: "memory");
}
__device__ __forceinline__ uint32_t smem_u32(const void* p) {
    uint32_t a;
    asm("{ .reg .u64 t; cvta.to.shared.u64 t, %1; cvt.u32.u64 %0, t; }"
        : "=r"(a) : "l"(p));
    return a;
}

// ---------------------------------------------------------------------------
// prepass
// ---------------------------------------------------------------------------
__global__ __launch_bounds__(256) void x2h_kernel(
    const float* __restrict__ x, __half* __restrict__ xh)
{
    size_t i = ((size_t)blockIdx.x * 256 + threadIdx.x) * 4;
    if (i < (size_t)MROWS * DMODEL) {
        float4 v = *reinterpret_cast<const float4*>(x + i);
        __half2 h0 = __floats2half2_rn(v.x, v.y);
        __half2 h1 = __floats2half2_rn(v.z, v.w);
        *reinterpret_cast<uint2*>(xh + i) =
            make_uint2(*(uint32_t*)&h0, *(uint32_t*)&h1);
    }
}

__global__ __launch_bounds__(256) void transpose_h_kernel(
    const float* __restrict__ W, __half* __restrict__ Wt, int K, int N)
{
    __shared__ float t[32][33];
    const int kb = blockIdx.x * 32, nb = blockIdx.y * 32;
    const int tx = threadIdx.x, ty = threadIdx.y;   // 32 x 8
#pragma unroll
    for (int i = 0; i < 32; i += 8)
        t[ty + i][tx] = W[(size_t)(kb + ty + i) * N + nb + tx];
    __syncthreads();
#pragma unroll
    for (int i = 0; i < 32; i += 8)
        Wt[(size_t)(nb + ty + i) * K + kb + tx] = __float2half_rn(t[tx][ty + i]);
}

// ---------------------------------------------------------------------------
// fp16 GEMM, m16n8k16 + ldmatrix + cp.async 3-stage pipeline.
// CTA tile 128x256, BK=32 halves; 8 warps (wm2 x wn4), warp tile 64x64.
// ---------------------------------------------------------------------------
#define GM 128
#define GN 256
#define GKH 32
#define ASTR_B 80                      // bytes per A/B smem row (40 halves)
#define A_BYTES (GM * ASTR_B)          // 10240
#define B_BYTES (GN * ASTR_B)          // 20480
#define STAGE_BYTES (A_BYTES + B_BYTES)
#define GEMM_SMEM_BYTES (3 * STAGE_BYTES)   // 92160

template <int HALF_OUT>
__global__ __launch_bounds__(256, 1) void gemm_f16_kernel(
    const __half* __restrict__ A, const __half* __restrict__ Bt,
    const float* __restrict__ bias, void* __restrict__ Cv,
    int M, int N, int K)
{
    extern __shared__ uint32_t smw[];
    const int tid  = threadIdx.x;
    const int warp = tid >> 5;
    const int lane = tid & 31;
    const int grp  = lane >> 2;
    const int qid  = lane & 3;
    const int wm   = warp & 1;
    const int wn   = warp >> 1;
    const int rowBase = blockIdx.y * GM;
    const int colBase = blockIdx.x * GN;

    const __half* Ap = A + (size_t)rowBase * K;
    const __half* Bp = Bt + (size_t)colBase * K;
    const uint32_t sbase = smem_u32(smw);

    float acc[4][8][4];
#pragma unroll
    for (int mt = 0; mt < 4; mt++)
#pragma unroll
        for (int nt = 0; nt < 8; nt++)
#pragma unroll
            for (int v = 0; v < 4; v++) acc[mt][nt][v] = 0.f;

    const int nchunk = K / GKH;

    auto issue_stage = [&](int c) {
        const uint32_t abase = sbase + (c % 3) * STAGE_BYTES;
        const uint32_t bbase = abase + A_BYTES;
        const int k0 = c * GKH;
        {
            int id0 = tid * 2;
            int r = id0 >> 2, q = id0 & 3;      // q in {0,2}
            const __half* src = Ap + (size_t)r * K + k0 + q * 8;
            cp16(abase + r * ASTR_B + q * 16, src);
            cp16(abase + r * ASTR_B + (q + 1) * 16, src + 8);
        }
#pragma unroll
        for (int i = 0; i < 4; i++) {
            int id = tid + i * 256;
            int r = id >> 2, q = id & 3;
            cp16(bbase + r * ASTR_B + q * 16,
                 Bp + (size_t)r * K + k0 + q * 8);
        }
        cp_commit();
    };

    issue_stage(0);
    issue_stage(1);

    // ldmatrix lane-address offsets
    const uint32_t a_off = (uint32_t)(lane & 15) * ASTR_B + (uint32_t)(lane >> 4) * 16;
    const uint32_t b_off = (uint32_t)((lane & 7) + ((lane >> 4) << 3)) * ASTR_B
                         + (uint32_t)((lane >> 3) & 1) * 16;

    for (int c = 0; c < nchunk; c++) {
        cp_wait1();
        __syncthreads();
        if (c + 2 < nchunk) issue_stage(c + 2);
        else cp_commit();

        const uint32_t abase = sbase + (c % 3) * STAGE_BYTES;
        const uint32_t bbase = abase + A_BYTES;

#pragma unroll
        for (int s = 0; s < 2; s++) {
            const uint32_t kb = s * 32;
            uint32_t af[4][4];
#pragma unroll
            for (int mt = 0; mt < 4; mt++)
                ldm_x4(af[mt][0], af[mt][1], af[mt][2], af[mt][3],
                       abase + (wm * 64 + mt * 16) * ASTR_B + a_off + kb);
#pragma unroll
            for (int ntp = 0; ntp < 4; ntp++) {
                uint32_t b0, b1, b2, b3;
                ldm_x4(b0, b1, b2, b3,
                       bbase + (wn * 64 + ntp * 16) * ASTR_B + b_off + kb);
#pragma unroll
                for (int mt = 0; mt < 4; mt++) {
                    mma_f16(acc[mt][2 * ntp][0], acc[mt][2 * ntp][1],
                            acc[mt][2 * ntp][2], acc[mt][2 * ntp][3],
                            af[mt][0], af[mt][1], af[mt][2], af[mt][3], b0, b1);
                    mma_f16(acc[mt][2 * ntp + 1][0], acc[mt][2 * ntp + 1][1],
                            acc[mt][2 * ntp + 1][2], acc[mt][2 * ntp + 1][3],
                            af[mt][0], af[mt][1], af[mt][2], af[mt][3], b2, b3);
                }
            }
        }
    }

#pragma unroll
    for (int mt = 0; mt < 4; mt++) {
#pragma unroll
        for (int nt = 0; nt < 8; nt++) {
            int c = colBase + wn * 64 + nt * 8 + 2 * qid;
            float bx = bias[c], by = bias[c + 1];
            int r0 = rowBase + wm * 64 + mt * 16 + grp;
            if (HALF_OUT) {
                __half* C = (__half*)Cv;
                __half2 o0 = __floats2half2_rn(acc[mt][nt][0] + bx, acc[mt][nt][1] + by);
                *reinterpret_cast<__half2*>(C + (size_t)r0 * N + c) = o0;
                __half2 o1 = __floats2half2_rn(acc[mt][nt][2] + bx, acc[mt][nt][3] + by);
                *reinterpret_cast<__half2*>(C + (size_t)(r0 + 8) * N + c) = o1;
            } else {
                float* C = (float*)Cv;
                float2 o0 = make_float2(acc[mt][nt][0] + bx, acc[mt][nt][1] + by);
                *reinterpret_cast<float2*>(C + (size_t)r0 * N + c) = o0;
                float2 o1 = make_float2(acc[mt][nt][2] + bx, acc[mt][nt][3] + by);
                *reinterpret_cast<float2*>(C + (size_t)(r0 + 8) * N + c) = o1;
            }
        }
    }
}

// ---------------------------------------------------------------------------
// Fused flash attention, fp16 mma + ldmatrix.
// smem halves: Ks[128][88] | Vs[64][136] (V transposed) | Ps[128][136]
// ---------------------------------------------------------------------------
#define KS_W 44
#define VS_W 68
#define PS_W 68
#define KS_B 176                              // bytes/row
#define VS_B 272
#define PS_B 272
#define KS_OFFW 0
#define VS_OFFW (128 * KS_W)                  // 5632
#define PS_OFFW (VS_OFFW + 64 * VS_W)         // 9984
#define FA_SMEM_WORDS (PS_OFFW + 128 * PS_W)  // 18688
#define FA_SMEM_BYTES (FA_SMEM_WORDS * 4)     // 74752

__global__ __launch_bounds__(256) void fa_kernel(
    const __half* __restrict__ qkv, __half* __restrict__ att)
{
    extern __shared__ uint32_t smw[];
    uint32_t* Ks = smw + KS_OFFW;
    uint32_t* Vs = smw + VS_OFFW;
    uint32_t* Ps = smw + PS_OFFW;
    __half*  Vsh = reinterpret_cast<__half*>(Vs);

    const int qb = 15 - blockIdx.x;
    const int bh = blockIdx.y;
    const int b = bh >> 4, h = bh & 15;
    const __half* Qp = qkv + (size_t)b * SEQ * QKVN + h * HDIM;
    const __half* Kp = Qp + DMODEL;
    const __half* Vp = Qp + 2 * DMODEL;

    const int tid = threadIdx.x, warp = tid >> 5, lane = tid & 31;
    const int grp = lane >> 2, qid = lane & 3;

    const uint32_t ks_base = smem_u32(smw) + KS_OFFW * 4;
    const uint32_t vs_base = smem_u32(smw) + VS_OFFW * 4;
    const uint32_t ps_base = smem_u32(smw) + PS_OFFW * 4;

    // ldmatrix lane offsets
    const uint32_t aK_off = (uint32_t)(warp * 16 + (lane & 15)) * KS_B
                          + (uint32_t)(lane >> 4) * 16;
    const uint32_t bK_off = (uint32_t)((lane & 7) + ((lane >> 4) << 3)) * KS_B
                          + (uint32_t)((lane >> 3) & 1) * 16;
    const uint32_t aP_off = (uint32_t)(warp * 16 + (lane & 15)) * PS_B
                          + (uint32_t)(lane >> 4) * 16;
    const uint32_t bV_off = (uint32_t)((lane & 7) + ((lane >> 4) << 3)) * VS_B
                          + (uint32_t)((lane >> 3) & 1) * 16;

    // ---- stage Q (scaled 0.125) into Ks rows ----
    {
        const __half2 sc = __floats2half2_rn(0.125f, 0.125f);
#pragma unroll
        for (int i = 0; i < 4; i++) {
            int id = tid + i * 256;
            int r = id >> 3, u = id & 7;
            uint2 v = *reinterpret_cast<const uint2*>(
                Qp + (size_t)(qb * 128 + r) * QKVN + u * 8 + 0);
            uint2 w = *reinterpret_cast<const uint2*>(
                Qp + (size_t)(qb * 128 + r) * QKVN + u * 8 + 4);
            __half2 h0 = __hmul2(*(__half2*)&v.x, sc);
            __half2 h1 = __hmul2(*(__half2*)&v.y, sc);
            __half2 h2 = __hmul2(*(__half2*)&w.x, sc);
            __half2 h3 = __hmul2(*(__half2*)&w.y, sc);
            uint32_t* dst = Ks + r * KS_W + u * 4;
            dst[0] = *(uint32_t*)&h0; dst[1] = *(uint32_t*)&h1;
            dst[2] = *(uint32_t*)&h2; dst[3] = *(uint32_t*)&h3;
        }
    }
    __syncthreads();

    uint32_t aq[4][4];
#pragma unroll
    for (int s = 0; s < 4; s++)
        ldm_x4(aq[s][0], aq[s][1], aq[s][2], aq[s][3], ks_base + aK_off + s * 32);

    float m0v = -CUDART_INF_F, m1v = -CUDART_INF_F;
    float l0 = 0.f, l1 = 0.f;
    float acc_o[8][4];
#pragma unroll
    for (int j = 0; j < 8; j++)
#pragma unroll
        for (int v = 0; v < 4; v++) acc_o[j][v] = 0.f;

    for (int kb = 0; kb <= qb; kb++) {
        __syncthreads();
#pragma unroll
        for (int i = 0; i < 4; i++) {
            int id = tid + i * 256;
            int r = id >> 3, u = id & 7;
            uint4 v = *reinterpret_cast<const uint4*>(
                Kp + (size_t)(kb * 128 + r) * QKVN + u * 8);
            uint32_t* dst = Ks + r * KS_W + u * 4;
            dst[0] = v.x; dst[1] = v.y; dst[2] = v.z; dst[3] = v.w;
        }
#pragma unroll
        for (int i = 0; i < 8; i++) {
            int id = tid + i * 256;
            int k = id >> 4, dg = id & 15;
            uint2 v = *reinterpret_cast<const uint2*>(
                Vp + (size_t)(kb * 128 + k) * QKVN + dg * 4);
            __half2 p0 = *(__half2*)&v.x;
            __half2 p1 = *(__half2*)&v.y;
            Vsh[(dg * 4 + 0) * (VS_W * 2) + k] = __low2half(p0);
            Vsh[(dg * 4 + 1) * (VS_W * 2) + k] = __high2half(p0);
            Vsh[(dg * 4 + 2) * (VS_W * 2) + k] = __low2half(p1);
            Vsh[(dg * 4 + 3) * (VS_W * 2) + k] = __high2half(p1);
        }
        __syncthreads();

        // ---- S = Q K^T ----
        float s_[16][4];
#pragma unroll
        for (int nt = 0; nt < 16; nt++)
#pragma unroll
            for (int v = 0; v < 4; v++) s_[nt][v] = 0.f;
#pragma unroll
        for (int s = 0; s < 4; s++) {
#pragma unroll
            for (int ntp = 0; ntp < 8; ntp++) {
                uint32_t b0, b1, b2, b3;
                ldm_x4(b0, b1, b2, b3, ks_base + ntp * 16 * KS_B + bK_off + s * 32);
                mma_f16(s_[2 * ntp][0], s_[2 * ntp][1], s_[2 * ntp][2], s_[2 * ntp][3],
                        aq[s][0], aq[s][1], aq[s][2], aq[s][3], b0, b1);
                mma_f16(s_[2 * ntp + 1][0], s_[2 * ntp + 1][1],
                        s_[2 * ntp + 1][2], s_[2 * ntp + 1][3],
                        aq[s][0], aq[s][1], aq[s][2], aq[s][3], b2, b3);
            }
        }

        if (kb == qb) {
            const int r0 = warp * 16 + grp, r1 = r0 + 8;
#pragma unroll
            for (int nt = 0; nt < 16; nt++) {
                int c = nt * 8 + 2 * qid;
                if (c > r0)     s_[nt][0] = -CUDART_INF_F;
                if (c + 1 > r0) s_[nt][1] = -CUDART_INF_F;
                if (c > r1)     s_[nt][2] = -CUDART_INF_F;
                if (c + 1 > r1) s_[nt][3] = -CUDART_INF_F;
            }
        }

        float mx0 = -CUDART_INF_F, mx1 = -CUDART_INF_F;
#pragma unroll
        for (int nt = 0; nt < 16; nt++) {
            mx0 = fmaxf(mx0, fmaxf(s_[nt][0], s_[nt][1]));
            mx1 = fmaxf(mx1, fmaxf(s_[nt][2], s_[nt][3]));
        }
        mx0 = fmaxf(mx0, __shfl_xor_sync(0xffffffffu, mx0, 1));
        mx0 = fmaxf(mx0, __shfl_xor_sync(0xffffffffu, mx0, 2));
        mx1 = fmaxf(mx1, __shfl_xor_sync(0xffffffffu, mx1, 1));
        mx1 = fmaxf(mx1, __shfl_xor_sync(0xffffffffu, mx1, 2));

        float mn0 = fmaxf(m0v, mx0), mn1 = fmaxf(m1v, mx1);
        float a0 = __expf(m0v - mn0), a1 = __expf(m1v - mn1);

        const int pr0 = (warp * 16 + grp) * PS_W;
        const int pr1 = pr0 + 8 * PS_W;
        float sum0 = 0.f, sum1 = 0.f;
#pragma unroll
        for (int nt = 0; nt < 16; nt++) {
            float p0 = __expf(s_[nt][0] - mn0);
            float p1 = __expf(s_[nt][1] - mn0);
            float p2 = __expf(s_[nt][2] - mn1);
            float p3 = __expf(s_[nt][3] - mn1);
            sum0 += p0 + p1;
            sum1 += p2 + p3;
            __half2 q0 = __floats2half2_rn(p0, p1);
            __half2 q1 = __floats2half2_rn(p2, p3);
            Ps[pr0 + nt * 4 + qid] = *(uint32_t*)&q0;
            Ps[pr1 + nt * 4 + qid] = *(uint32_t*)&q1;
        }
        sum0 += __shfl_xor_sync(0xffffffffu, sum0, 1);
        sum0 += __shfl_xor_sync(0xffffffffu, sum0, 2);
        sum1 += __shfl_xor_sync(0xffffffffu, sum1, 1);
        sum1 += __shfl_xor_sync(0xffffffffu, sum1, 2);
        l0 = l0 * a0 + sum0;
        l1 = l1 * a1 + sum1;
        m0v = mn0; m1v = mn1;

#pragma unroll
        for (int nt = 0; nt < 8; nt++) {
            acc_o[nt][0] *= a0; acc_o[nt][1] *= a0;
            acc_o[nt][2] *= a1; acc_o[nt][3] *= a1;
        }

        // ---- O += P V ----
#pragma unroll
        for (int s = 0; s < 8; s++) {
            uint32_t ap0, ap1, ap2, ap3;
            ldm_x4(ap0, ap1, ap2, ap3, ps_base + aP_off + s * 32);
#pragma unroll
            for (int ntp = 0; ntp < 4; ntp++) {
                uint32_t b0, b1, b2, b3;
                ldm_x4(b0, b1, b2, b3, vs_base + ntp * 16 * VS_B + bV_off + s * 32);
                mma_f16(acc_o[2 * ntp][0], acc_o[2 * ntp][1],
                        acc_o[2 * ntp][2], acc_o[2 * ntp][3],
                        ap0, ap1, ap2, ap3, b0, b1);
                mma_f16(acc_o[2 * ntp + 1][0], acc_o[2 * ntp + 1][1],
                        acc_o[2 * ntp + 1][2], acc_o[2 * ntp + 1][3],
                        ap0, ap1, ap2, ap3, b2, b3);
            }
        }
    }

    // ---- epilogue ----
    const float inv0 = 1.f / l0, inv1 = 1.f / l1;
    const int r0 = qb * 128 + warp * 16 + grp;
#pragma unroll
    for (int nt = 0; nt < 8; nt++) {
        int col = h * HDIM + nt * 8 + 2 * qid;
        __half2 o0 = __floats2half2_rn(acc_o[nt][0] * inv0, acc_o[nt][1] * inv0);
        *reinterpret_cast<__half2*>(att + (size_t)(b * SEQ + r0) * DMODEL + col) = o0;
        __half2 o1 = __floats2half2_rn(acc_o[nt][2] * inv1, acc_o[nt][3] * inv1);
        *reinterpret_cast<__half2*>(att + (size_t)(b * SEQ + r0 + 8) * DMODEL + col) = o1;
    }
}

// ---------------------------------------------------------------------------
extern "C" void kernel_launch(void* const* d_in, const int* in_sizes, int n_in,
                              void* d_out, int out_size)
{
    const float* x    = (const float*)d_in[0];
    const float* Wqkv = (const float*)d_in[1];
    const float* bqkv = (const float*)d_in[2];
    const float* Wp   = (const float*)d_in[3];
    const float* bp   = (const float*)d_in[4];
    float* out = (float*)d_out;

    __half *qkv, *att, *xh, *wqkv_t, *wp_t;
    cudaGetSymbolAddress((void**)&qkv, g_qkv);
    cudaGetSymbolAddress((void**)&att, g_att);
    cudaGetSymbolAddress((void**)&xh, g_xh);
    cudaGetSymbolAddress((void**)&wqkv_t, g_wqkv_t);
    cudaGetSymbolAddress((void**)&wp_t, g_wp_t);

    cudaFuncSetAttribute(fa_kernel,
                         cudaFuncAttributeMaxDynamicSharedMemorySize, FA_SMEM_BYTES);
    cudaFuncSetAttribute(gemm_f16_kernel<1>,
                         cudaFuncAttributeMaxDynamicSharedMemorySize, GEMM_SMEM_BYTES);
    cudaFuncSetAttribute(gemm_f16_kernel<0>,
                         cudaFuncAttributeMaxDynamicSharedMemorySize, GEMM_SMEM_BYTES);

    x2h_kernel<<<(MROWS * DMODEL / 4 + 255) / 256, 256>>>(x, xh);
    {
        dim3 blk(32, 8);
        transpose_h_kernel<<<dim3(DMODEL / 32, QKVN / 32), blk>>>(Wqkv, wqkv_t, DMODEL, QKVN);
        transpose_h_kernel<<<dim3(DMODEL / 32, DMODEL / 32), blk>>>(Wp, wp_t, DMODEL, DMODEL);
    }
    {
        dim3 grid(QKVN / GN, MROWS / GM);
        gemm_f16_kernel<1><<<grid, 256, GEMM_SMEM_BYTES>>>(xh, wqkv_t, bqkv, qkv,
                                                           MROWS, QKVN, DMODEL);
    }
    {
        dim3 grid(SEQ / 128, BH);
        fa_kernel<<<grid, 256, FA_SMEM_BYTES>>>(qkv, att);
    }
    {
        dim3 grid(DMODEL / GN, MROWS / GM);
        gemm_f16_kernel<0><<<grid, 256, GEMM_SMEM_BYTES>>>(att, wp_t, bp, out,
                                                           MROWS, DMODEL, DMODEL);
    }
}

// round 8
// speedup vs baseline: 5.8762x; 1.0170x over previous
#include <cuda_runtime.h>
#include <cuda_fp16.h>
#include <math_constants.h>
#include <cstdint>

#define Bsz 4
#define SEQ 2048
#define DMODEL 1024
#define NHEAD 16
#define HDIM 64
#define BH (Bsz * NHEAD)          // 64
#define MROWS (Bsz * SEQ)         // 8192
#define QKVN (3 * DMODEL)         // 3072

__device__ __half g_qkv[MROWS * QKVN];
__device__ __half g_att[MROWS * DMODEL];
__device__ __half g_xh[MROWS * DMODEL];
__device__ __half g_wqkv_t[QKVN * DMODEL];   // [3072][1024] K-major
__device__ __half g_wp_t[DMODEL * DMODEL];   // [1024][1024] K-major

// ---------------------------------------------------------------------------
__device__ __forceinline__ void mma_f16(
    float& d0, float& d1, float& d2, float& d3,
    uint32_t a0, uint32_t a1, uint32_t a2, uint32_t a3,
    uint32_t b0, uint32_t b1)
{
    asm volatile(
        "mma.sync.aligned.m16n8k16.row.col.f32.f16.f16.f32 "
        "{%0,%1,%2,%3}, {%4,%5,%6,%7}, {%8,%9}, {%0,%1,%2,%3};\n"
        : "+f"(d0), "+f"(d1), "+f"(d2), "+f"(d3)
        : "r"(a0), "r"(a1), "r"(a2), "r"(a3), "r"(b0), "r"(b1));
}

__device__ __forceinline__ void ldm_x4(
    uint32_t& r0, uint32_t& r1, uint32_t& r2, uint32_t& r3, uint32_t addr)
{
    asm volatile("ldmatrix.sync.aligned.m8n8.x4.shared.b16 {%0,%1,%2,%3}, [%4];"
        : "=r"(r0), "=r"(r1), "=r"(r2), "=r"(r3) : "r"(addr));
}

__device__ __forceinline__ void cp16(uint32_t dst, const void* src) {
    asm volatile("cp.async.cg.shared.global [%0], [%1], 16;"
                 :: "r"(dst), "l"(src) : "memory");
}
__device__ __forceinline__ void cp_commit() {
    asm volatile("cp.async.commit_group;" ::: "memory");
}
__device__ __forceinline__ void cp_wait1() {
    asm volatile("cp.async.wait_group 1;" ::: "memory");
}
__device__ __forceinline__ uint32_t smem_u32(const void* p) {
    uint32_t a;
    asm("{ .reg .u64 t; cvta.to.shared.u64 t, %1; cvt.u32.u64 %0, t; }"
        : "=r"(a) : "l"(p));
    return a;
}

// ---------------------------------------------------------------------------
// prepass
// ---------------------------------------------------------------------------
__global__ __launch_bounds__(256) void x2h_kernel(
    const float* __restrict__ x, __half* __restrict__ xh)
{
    size_t i = ((size_t)blockIdx.x * 256 + threadIdx.x) * 4;
    if (i < (size_t)MROWS * DMODEL) {
        float4 v = *reinterpret_cast<const float4*>(x + i);
        __half2 h0 = __floats2half2_rn(v.x, v.y);
        __half2 h1 = __floats2half2_rn(v.z, v.w);
        *reinterpret_cast<uint2*>(xh + i) =
            make_uint2(*(uint32_t*)&h0, *(uint32_t*)&h1);
    }
}

__global__ __launch_bounds__(256) void transpose_h_kernel(
    const float* __restrict__ W, __half* __restrict__ Wt, int K, int N)
{
    __shared__ float t[32][33];
    const int kb = blockIdx.x * 32, nb = blockIdx.y * 32;
    const int tx = threadIdx.x, ty = threadIdx.y;   // 32 x 8
#pragma unroll
    for (int i = 0; i < 32; i += 8)
        t[ty + i][tx] = W[(size_t)(kb + ty + i) * N + nb + tx];
    __syncthreads();
#pragma unroll
    for (int i = 0; i < 32; i += 8)
        Wt[(size_t)(nb + ty + i) * K + kb + tx] = __float2half_rn(t[tx][ty + i]);
}

// ---------------------------------------------------------------------------
// fp16 GEMM, m16n8k16 + ldmatrix + cp.async 3-stage pipeline.
// CTA tile 128x256, BK=32 halves; 512 threads = 16 warps (wm4 x wn4),
// warp tile 32x64 (mt2 x nt8).
// ---------------------------------------------------------------------------
#define GM 128
#define GN 256
#define GKH 32
#define ASTR_B 80                      // bytes per A/B smem row (40 halves)
#define A_BYTES (GM * ASTR_B)          // 10240
#define B_BYTES (GN * ASTR_B)          // 20480
#define STAGE_BYTES (A_BYTES + B_BYTES)
#define GEMM_SMEM_BYTES (3 * STAGE_BYTES)   // 92160
#define GT 512

template <int HALF_OUT>
__global__ __launch_bounds__(GT, 1) void gemm_f16_kernel(
    const __half* __restrict__ A, const __half* __restrict__ Bt,
    const float* __restrict__ bias, void* __restrict__ Cv,
    int M, int N, int K)
{
    extern __shared__ uint32_t smw[];
    const int tid  = threadIdx.x;
    const int warp = tid >> 5;
    const int lane = tid & 31;
    const int grp  = lane >> 2;
    const int qid  = lane & 3;
    const int wm   = warp & 3;      // 4 M-warps
    const int wn   = warp >> 2;     // 4 N-warps
    const int rowBase = blockIdx.y * GM;
    const int colBase = blockIdx.x * GN;

    const __half* Ap = A + (size_t)rowBase * K;
    const __half* Bp = Bt + (size_t)colBase * K;
    const uint32_t sbase = smem_u32(smw);

    float acc[2][8][4];
#pragma unroll
    for (int mt = 0; mt < 2; mt++)
#pragma unroll
        for (int nt = 0; nt < 8; nt++)
#pragma unroll
            for (int v = 0; v < 4; v++) acc[mt][nt][v] = 0.f;

    const int nchunk = K / GKH;

    auto issue_stage = [&](int c) {
        const uint32_t abase = sbase + (c % 3) * STAGE_BYTES;
        const uint32_t bbase = abase + A_BYTES;
        const int k0 = c * GKH;
        // A: 128 rows x 4 x 16B = 512 chunks; one per thread
        {
            int r = tid >> 2, q = tid & 3;
            cp16(abase + r * ASTR_B + q * 16,
                 Ap + (size_t)r * K + k0 + q * 8);
        }
        // B: 256 rows x 4 = 1024 chunks; two per thread
#pragma unroll
        for (int i = 0; i < 2; i++) {
            int id = tid + i * GT;
            int r = id >> 2, q = id & 3;
            cp16(bbase + r * ASTR_B + q * 16,
                 Bp + (size_t)r * K + k0 + q * 8);
        }
        cp_commit();
    };

    issue_stage(0);
    issue_stage(1);

    // ldmatrix lane-address offsets
    const uint32_t a_off = (uint32_t)(lane & 15) * ASTR_B + (uint32_t)(lane >> 4) * 16;
    const uint32_t b_off = (uint32_t)((lane & 7) + ((lane >> 4) << 3)) * ASTR_B
                         + (uint32_t)((lane >> 3) & 1) * 16;

    for (int c = 0; c < nchunk; c++) {
        cp_wait1();
        __syncthreads();
        if (c + 2 < nchunk) issue_stage(c + 2);
        else cp_commit();

        const uint32_t abase = sbase + (c % 3) * STAGE_BYTES;
        const uint32_t bbase = abase + A_BYTES;

#pragma unroll
        for (int s = 0; s < 2; s++) {
            const uint32_t kb = s * 32;
            uint32_t af[2][4];
#pragma unroll
            for (int mt = 0; mt < 2; mt++)
                ldm_x4(af[mt][0], af[mt][1], af[mt][2], af[mt][3],
                       abase + (wm * 32 + mt * 16) * ASTR_B + a_off + kb);
#pragma unroll
            for (int ntp = 0; ntp < 4; ntp++) {
                uint32_t b0, b1, b2, b3;
                ldm_x4(b0, b1, b2, b3,
                       bbase + (wn * 64 + ntp * 16) * ASTR_B + b_off + kb);
#pragma unroll
                for (int mt = 0; mt < 2; mt++) {
                    mma_f16(acc[mt][2 * ntp][0], acc[mt][2 * ntp][1],
                            acc[mt][2 * ntp][2], acc[mt][2 * ntp][3],
                            af[mt][0], af[mt][1], af[mt][2], af[mt][3], b0, b1);
                    mma_f16(acc[mt][2 * ntp + 1][0], acc[mt][2 * ntp + 1][1],
                            acc[mt][2 * ntp + 1][2], acc[mt][2 * ntp + 1][3],
                            af[mt][0], af[mt][1], af[mt][2], af[mt][3], b2, b3);
                }
            }
        }
    }

#pragma unroll
    for (int mt = 0; mt < 2; mt++) {
#pragma unroll
        for (int nt = 0; nt < 8; nt++) {
            int c = colBase + wn * 64 + nt * 8 + 2 * qid;
            float bx = bias[c], by = bias[c + 1];
            int r0 = rowBase + wm * 32 + mt * 16 + grp;
            if (HALF_OUT) {
                __half* C = (__half*)Cv;
                __half2 o0 = __floats2half2_rn(acc[mt][nt][0] + bx, acc[mt][nt][1] + by);
                *reinterpret_cast<__half2*>(C + (size_t)r0 * N + c) = o0;
                __half2 o1 = __floats2half2_rn(acc[mt][nt][2] + bx, acc[mt][nt][3] + by);
                *reinterpret_cast<__half2*>(C + (size_t)(r0 + 8) * N + c) = o1;
            } else {
                float* C = (float*)Cv;
                float2 o0 = make_float2(acc[mt][nt][0] + bx, acc[mt][nt][1] + by);
                *reinterpret_cast<float2*>(C + (size_t)r0 * N + c) = o0;
                float2 o1 = make_float2(acc[mt][nt][2] + bx, acc[mt][nt][3] + by);
                *reinterpret_cast<float2*>(C + (size_t)(r0 + 8) * N + c) = o1;
            }
        }
    }
}

// ---------------------------------------------------------------------------
// Fused flash attention, fp16 mma + ldmatrix. (unchanged from R7)
// smem halves: Ks[128][88] | Vs[64][136] (V transposed) | Ps[128][136]
// ---------------------------------------------------------------------------
#define KS_W 44
#define VS_W 68
#define PS_W 68
#define KS_B 176
#define VS_B 272
#define PS_B 272
#define KS_OFFW 0
#define VS_OFFW (128 * KS_W)
#define PS_OFFW (VS_OFFW + 64 * VS_W)
#define FA_SMEM_WORDS (PS_OFFW + 128 * PS_W)
#define FA_SMEM_BYTES (FA_SMEM_WORDS * 4)     // 74752

__global__ __launch_bounds__(256) void fa_kernel(
    const __half* __restrict__ qkv, __half* __restrict__ att)
{
    extern __shared__ uint32_t smw[];
    uint32_t* Ks = smw + KS_OFFW;
    uint32_t* Vs = smw + VS_OFFW;
    uint32_t* Ps = smw + PS_OFFW;
    __half*  Vsh = reinterpret_cast<__half*>(Vs);

    const int qb = 15 - blockIdx.x;
    const int bh = blockIdx.y;
    const int b = bh >> 4, h = bh & 15;
    const __half* Qp = qkv + (size_t)b * SEQ * QKVN + h * HDIM;
    const __half* Kp = Qp + DMODEL;
    const __half* Vp = Qp + 2 * DMODEL;

    const int tid = threadIdx.x, warp = tid >> 5, lane = tid & 31;
    const int grp = lane >> 2, qid = lane & 3;

    const uint32_t ks_base = smem_u32(smw) + KS_OFFW * 4;
    const uint32_t vs_base = smem_u32(smw) + VS_OFFW * 4;
    const uint32_t ps_base = smem_u32(smw) + PS_OFFW * 4;

    const uint32_t aK_off = (uint32_t)(warp * 16 + (lane & 15)) * KS_B
                          + (uint32_t)(lane >> 4) * 16;
    const uint32_t bK_off = (uint32_t)((lane & 7) + ((lane >> 4) << 3)) * KS_B
                          + (uint32_t)((lane >> 3) & 1) * 16;
    const uint32_t aP_off = (uint32_t)(warp * 16 + (lane & 15)) * PS_B
                          + (uint32_t)(lane >> 4) * 16;
    const uint32_t bV_off = (uint32_t)((lane & 7) + ((lane >> 4) << 3)) * VS_B
                          + (uint32_t)((lane >> 3) & 1) * 16;

    {
        const __half2 sc = __floats2half2_rn(0.125f, 0.125f);
#pragma unroll
        for (int i = 0; i < 4; i++) {
            int id = tid + i * 256;
            int r = id >> 3, u = id & 7;
            uint2 v = *reinterpret_cast<const uint2*>(
                Qp + (size_t)(qb * 128 + r) * QKVN + u * 8 + 0);
            uint2 w = *reinterpret_cast<const uint2*>(
                Qp + (size_t)(qb * 128 + r) * QKVN + u * 8 + 4);
            __half2 h0 = __hmul2(*(__half2*)&v.x, sc);
            __half2 h1 = __hmul2(*(__half2*)&v.y, sc);
            __half2 h2 = __hmul2(*(__half2*)&w.x, sc);
            __half2 h3 = __hmul2(*(__half2*)&w.y, sc);
            uint32_t* dst = Ks + r * KS_W + u * 4;
            dst[0] = *(uint32_t*)&h0; dst[1] = *(uint32_t*)&h1;
            dst[2] = *(uint32_t*)&h2; dst[3] = *(uint32_t*)&h3;
        }
    }
    __syncthreads();

    uint32_t aq[4][4];
#pragma unroll
    for (int s = 0; s < 4; s++)
        ldm_x4(aq[s][0], aq[s][1], aq[s][2], aq[s][3], ks_base + aK_off + s * 32);

    float m0v = -CUDART_INF_F, m1v = -CUDART_INF_F;
    float l0 = 0.f, l1 = 0.f;
    float acc_o[8][4];
#pragma unroll
    for (int j = 0; j < 8; j++)
#pragma unroll
        for (int v = 0; v < 4; v++) acc_o[j][v] = 0.f;

    for (int kb = 0; kb <= qb; kb++) {
        __syncthreads();
#pragma unroll
        for (int i = 0; i < 4; i++) {
            int id = tid + i * 256;
            int r = id >> 3, u = id & 7;
            uint4 v = *reinterpret_cast<const uint4*>(
                Kp + (size_t)(kb * 128 + r) * QKVN + u * 8);
            uint32_t* dst = Ks + r * KS_W + u * 4;
            dst[0] = v.x; dst[1] = v.y; dst[2] = v.z; dst[3] = v.w;
        }
#pragma unroll
        for (int i = 0; i < 8; i++) {
            int id = tid + i * 256;
            int k = id >> 4, dg = id & 15;
            uint2 v = *reinterpret_cast<const uint2*>(
                Vp + (size_t)(kb * 128 + k) * QKVN + dg * 4);
            __half2 p0 = *(__half2*)&v.x;
            __half2 p1 = *(__half2*)&v.y;
            Vsh[(dg * 4 + 0) * (VS_W * 2) + k] = __low2half(p0);
            Vsh[(dg * 4 + 1) * (VS_W * 2) + k] = __high2half(p0);
            Vsh[(dg * 4 + 2) * (VS_W * 2) + k] = __low2half(p1);
            Vsh[(dg * 4 + 3) * (VS_W * 2) + k] = __high2half(p1);
        }
        __syncthreads();

        float s_[16][4];
#pragma unroll
        for (int nt = 0; nt < 16; nt++)
#pragma unroll
            for (int v = 0; v < 4; v++) s_[nt][v] = 0.f;
#pragma unroll
        for (int s = 0; s < 4; s++) {
#pragma unroll
            for (int ntp = 0; ntp < 8; ntp++) {
                uint32_t b0, b1, b2, b3;
                ldm_x4(b0, b1, b2, b3, ks_base + ntp * 16 * KS_B + bK_off + s * 32);
                mma_f16(s_[2 * ntp][0], s_[2 * ntp][1], s_[2 * ntp][2], s_[2 * ntp][3],
                        aq[s][0], aq[s][1], aq[s][2], aq[s][3], b0, b1);
                mma_f16(s_[2 * ntp + 1][0], s_[2 * ntp + 1][1],
                        s_[2 * ntp + 1][2], s_[2 * ntp + 1][3],
                        aq[s][0], aq[s][1], aq[s][2], aq[s][3], b2, b3);
            }
        }

        if (kb == qb) {
            const int r0 = warp * 16 + grp, r1 = r0 + 8;
#pragma unroll
            for (int nt = 0; nt < 16; nt++) {
                int c = nt * 8 + 2 * qid;
                if (c > r0)     s_[nt][0] = -CUDART_INF_F;
                if (c + 1 > r0) s_[nt][1] = -CUDART_INF_F;
                if (c > r1)     s_[nt][2] = -CUDART_INF_F;
                if (c + 1 > r1) s_[nt][3] = -CUDART_INF_F;
            }
        }

        float mx0 = -CUDART_INF_F, mx1 = -CUDART_INF_F;
#pragma unroll
        for (int nt = 0; nt < 16; nt++) {
            mx0 = fmaxf(mx0, fmaxf(s_[nt][0], s_[nt][1]));
            mx1 = fmaxf(mx1, fmaxf(s_[nt][2], s_[nt][3]));
        }
        mx0 = fmaxf(mx0, __shfl_xor_sync(0xffffffffu, mx0, 1));
        mx0 = fmaxf(mx0, __shfl_xor_sync(0xffffffffu, mx0, 2));
        mx1 = fmaxf(mx1, __shfl_xor_sync(0xffffffffu, mx1, 1));
        mx1 = fmaxf(mx1, __shfl_xor_sync(0xffffffffu, mx1, 2));

        float mn0 = fmaxf(m0v, mx0), mn1 = fmaxf(m1v, mx1);
        float a0 = __expf(m0v - mn0), a1 = __expf(m1v - mn1);

        const int pr0 = (warp * 16 + grp) * PS_W;
        const int pr1 = pr0 + 8 * PS_W;
        float sum0 = 0.f, sum1 = 0.f;
#pragma unroll
        for (int nt = 0; nt < 16; nt++) {
            float p0 = __expf(s_[nt][0] - mn0);
            float p1 = __expf(s_[nt][1] - mn0);
            float p2 = __expf(s_[nt][2] - mn1);
            float p3 = __expf(s_[nt][3] - mn1);
            sum0 += p0 + p1;
            sum1 += p2 + p3;
            __half2 q0 = __floats2half2_rn(p0, p1);
            __half2 q1 = __floats2half2_rn(p2, p3);
            Ps[pr0 + nt * 4 + qid] = *(uint32_t*)&q0;
            Ps[pr1 + nt * 4 + qid] = *(uint32_t*)&q1;
        }
        sum0 += __shfl_xor_sync(0xffffffffu, sum0, 1);
        sum0 += __shfl_xor_sync(0xffffffffu, sum0, 2);
        sum1 += __shfl_xor_sync(0xffffffffu, sum1, 1);
        sum1 += __shfl_xor_sync(0xffffffffu, sum1, 2);
        l0 = l0 * a0 + sum0;
        l1 = l1 * a1 + sum1;
        m0v = mn0; m1v = mn1;

#pragma unroll
        for (int nt = 0; nt < 8; nt++) {
            acc_o[nt][0] *= a0; acc_o[nt][1] *= a0;
            acc_o[nt][2] *= a1; acc_o[nt][3] *= a1;
        }

#pragma unroll
        for (int s = 0; s < 8; s++) {
            uint32_t ap0, ap1, ap2, ap3;
            ldm_x4(ap0, ap1, ap2, ap3, ps_base + aP_off + s * 32);
#pragma unroll
            for (int ntp = 0; ntp < 4; ntp++) {
                uint32_t b0, b1, b2, b3;
                ldm_x4(b0, b1, b2, b3, vs_base + ntp * 16 * VS_B + bV_off + s * 32);
                mma_f16(acc_o[2 * ntp][0], acc_o[2 * ntp][1],
                        acc_o[2 * ntp][2], acc_o[2 * ntp][3],
                        ap0, ap1, ap2, ap3, b0, b1);
                mma_f16(acc_o[2 * ntp + 1][0], acc_o[2 * ntp + 1][1],
                        acc_o[2 * ntp + 1][2], acc_o[2 * ntp + 1][3],
                        ap0, ap1, ap2, ap3, b2, b3);
            }
        }
    }

    const float inv0 = 1.f / l0, inv1 = 1.f / l1;
    const int r0 = qb * 128 + warp * 16 + grp;
#pragma unroll
    for (int nt = 0; nt < 8; nt++) {
        int col = h * HDIM + nt * 8 + 2 * qid;
        __half2 o0 = __floats2half2_rn(acc_o[nt][0] * inv0, acc_o[nt][1] * inv0);
        *reinterpret_cast<__half2*>(att + (size_t)(b * SEQ + r0) * DMODEL + col) = o0;
        __half2 o1 = __floats2half2_rn(acc_o[nt][2] * inv1, acc_o[nt][3] * inv1);
        *reinterpret_cast<__half2*>(att + (size_t)(b * SEQ + r0 + 8) * DMODEL + col) = o1;
    }
}

// ---------------------------------------------------------------------------
extern "C" void kernel_launch(void* const* d_in, const int* in_sizes, int n_in,
                              void* d_out, int out_size)
{
    const float* x    = (const float*)d_in[0];
    const float* Wqkv = (const float*)d_in[1];
    const float* bqkv = (const float*)d_in[2];
    const float* Wp   = (const float*)d_in[3];
    const float* bp   = (const float*)d_in[4];
    float* out = (float*)d_out;

    __half *qkv, *att, *xh, *wqkv_t, *wp_t;
    cudaGetSymbolAddress((void**)&qkv, g_qkv);
    cudaGetSymbolAddress((void**)&att, g_att);
    cudaGetSymbolAddress((void**)&xh, g_xh);
    cudaGetSymbolAddress((void**)&wqkv_t, g_wqkv_t);
    cudaGetSymbolAddress((void**)&wp_t, g_wp_t);

    cudaFuncSetAttribute(fa_kernel,
                         cudaFuncAttributeMaxDynamicSharedMemorySize, FA_SMEM_BYTES);
    cudaFuncSetAttribute(gemm_f16_kernel<1>,
                         cudaFuncAttributeMaxDynamicSharedMemorySize, GEMM_SMEM_BYTES);
    cudaFuncSetAttribute(gemm_f16_kernel<0>,
                         cudaFuncAttributeMaxDynamicSharedMemorySize, GEMM_SMEM_BYTES);

    x2h_kernel<<<(MROWS * DMODEL / 4 + 255) / 256, 256>>>(x, xh);
    {
        dim3 blk(32, 8);
        transpose_h_kernel<<<dim3(DMODEL / 32, QKVN / 32), blk>>>(Wqkv, wqkv_t, DMODEL, QKVN);
        transpose_h_kernel<<<dim3(DMODEL / 32, DMODEL / 32), blk>>>(Wp, wp_t, DMODEL, DMODEL);
    }
    {
        dim3 grid(QKVN / GN, MROWS / GM);
        gemm_f16_kernel<1><<<grid, GT, GEMM_SMEM_BYTES>>>(xh, wqkv_t, bqkv, qkv,
                                                          MROWS, QKVN, DMODEL);
    }
    {
        dim3 grid(SEQ / 128, BH);
        fa_kernel<<<grid, 256, FA_SMEM_BYTES>>>(qkv, att);
    }
    {
        dim3 grid(DMODEL / GN, MROWS / GM);
        gemm_f16_kernel<0><<<grid, GT, GEMM_SMEM_BYTES>>>(att, wp_t, bp, out,
                                                          MROWS, DMODEL, DMODEL);
    }
}

// round 9
// speedup vs baseline: 6.0264x; 1.0256x over previous
#include <cuda_runtime.h>
#include <cuda_fp16.h>
#include <math_constants.h>
#include <cstdint>

#define Bsz 4
#define SEQ 2048
#define DMODEL 1024
#define NHEAD 16
#define HDIM 64
#define BH (Bsz * NHEAD)          // 64
#define MROWS (Bsz * SEQ)         // 8192
#define QKVN (3 * DMODEL)         // 3072

__device__ __half g_qkv[MROWS * QKVN];
__device__ __half g_att[MROWS * DMODEL];
__device__ __half g_xh[MROWS * DMODEL];
__device__ __half g_wqkv_t[QKVN * DMODEL];   // [3072][1024] K-major
__device__ __half g_wp_t[DMODEL * DMODEL];   // [1024][1024] K-major

// ---------------------------------------------------------------------------
__device__ __forceinline__ void mma_f16(
    float& d0, float& d1, float& d2, float& d3,
    uint32_t a0, uint32_t a1, uint32_t a2, uint32_t a3,
    uint32_t b0, uint32_t b1)
{
    asm volatile(
        "mma.sync.aligned.m16n8k16.row.col.f32.f16.f16.f32 "
        "{%0,%1,%2,%3}, {%4,%5,%6,%7}, {%8,%9}, {%0,%1,%2,%3};\n"
        : "+f"(d0), "+f"(d1), "+f"(d2), "+f"(d3)
        : "r"(a0), "r"(a1), "r"(a2), "r"(a3), "r"(b0), "r"(b1));
}

__device__ __forceinline__ void ldm_x4(
    uint32_t& r0, uint32_t& r1, uint32_t& r2, uint32_t& r3, uint32_t addr)
{
    asm volatile("ldmatrix.sync.aligned.m8n8.x4.shared.b16 {%0,%1,%2,%3}, [%4];"
        : "=r"(r0), "=r"(r1), "=r"(r2), "=r"(r3) : "r"(addr));
}

__device__ __forceinline__ uint32_t h2exp2(uint32_t x) {
    uint32_t r;
    asm("ex2.approx.f16x2 %0, %1;" : "=r"(r) : "r"(x));
    return r;
}

__device__ __forceinline__ void cp16(uint32_t dst, const void* src) {
    asm volatile("cp.async.cg.shared.global [%0], [%1], 16;"
                 :: "r"(dst), "l"(src) : "memory");
}
__device__ __forceinline__ void cp_commit() {
    asm volatile("cp.async.commit_group;" ::: "memory");
}
__device__ __forceinline__ void cp_wait1() {
    asm volatile("cp.async.wait_group 1;" ::: "memory");
}
__device__ __forceinline__ uint32_t smem_u32(const void* p) {
    uint32_t a;
    asm("{ .reg .u64 t; cvta.to.shared.u64 t, %1; cvt.u32.u64 %0, t; }"
        : "=r"(a) : "l"(p));
    return a;
}

// ---------------------------------------------------------------------------
// prepass
// ---------------------------------------------------------------------------
__global__ __launch_bounds__(256) void x2h_kernel(
    const float* __restrict__ x, __half* __restrict__ xh)
{
    size_t i = ((size_t)blockIdx.x * 256 + threadIdx.x) * 4;
    if (i < (size_t)MROWS * DMODEL) {
        float4 v = *reinterpret_cast<const float4*>(x + i);
        __half2 h0 = __floats2half2_rn(v.x, v.y);
        __half2 h1 = __floats2half2_rn(v.z, v.w);
        *reinterpret_cast<uint2*>(xh + i) =
            make_uint2(*(uint32_t*)&h0, *(uint32_t*)&h1);
    }
}

__global__ __launch_bounds__(256) void transpose_h_kernel(
    const float* __restrict__ W, __half* __restrict__ Wt, int K, int N)
{
    __shared__ float t[32][33];
    const int kb = blockIdx.x * 32, nb = blockIdx.y * 32;
    const int tx = threadIdx.x, ty = threadIdx.y;   // 32 x 8
#pragma unroll
    for (int i = 0; i < 32; i += 8)
        t[ty + i][tx] = W[(size_t)(kb + ty + i) * N + nb + tx];
    __syncthreads();
#pragma unroll
    for (int i = 0; i < 32; i += 8)
        Wt[(size_t)(nb + ty + i) * K + kb + tx] = __float2half_rn(t[tx][ty + i]);
}

// ---------------------------------------------------------------------------
// fp16 GEMM (unchanged from R8): m16n8k16 + ldmatrix + cp.async 3-stage.
// CTA tile 128x256, BK=32 halves; 512 threads = 16 warps (wm4 x wn4).
// ---------------------------------------------------------------------------
#define GM 128
#define GN 256
#define GKH 32
#define ASTR_B 80
#define A_BYTES (GM * ASTR_B)
#define B_BYTES (GN * ASTR_B)
#define STAGE_BYTES (A_BYTES + B_BYTES)
#define GEMM_SMEM_BYTES (3 * STAGE_BYTES)   // 92160
#define GT 512

template <int HALF_OUT>
__global__ __launch_bounds__(GT, 1) void gemm_f16_kernel(
    const __half* __restrict__ A, const __half* __restrict__ Bt,
    const float* __restrict__ bias, void* __restrict__ Cv,
    int M, int N, int K)
{
    extern __shared__ uint32_t smw[];
    const int tid  = threadIdx.x;
    const int warp = tid >> 5;
    const int lane = tid & 31;
    const int grp  = lane >> 2;
    const int qid  = lane & 3;
    const int wm   = warp & 3;
    const int wn   = warp >> 2;
    const int rowBase = blockIdx.y * GM;
    const int colBase = blockIdx.x * GN;

    const __half* Ap = A + (size_t)rowBase * K;
    const __half* Bp = Bt + (size_t)colBase * K;
    const uint32_t sbase = smem_u32(smw);

    float acc[2][8][4];
#pragma unroll
    for (int mt = 0; mt < 2; mt++)
#pragma unroll
        for (int nt = 0; nt < 8; nt++)
#pragma unroll
            for (int v = 0; v < 4; v++) acc[mt][nt][v] = 0.f;

    const int nchunk = K / GKH;

    auto issue_stage = [&](int c) {
        const uint32_t abase = sbase + (c % 3) * STAGE_BYTES;
        const uint32_t bbase = abase + A_BYTES;
        const int k0 = c * GKH;
        {
            int r = tid >> 2, q = tid & 3;
            cp16(abase + r * ASTR_B + q * 16,
                 Ap + (size_t)r * K + k0 + q * 8);
        }
#pragma unroll
        for (int i = 0; i < 2; i++) {
            int id = tid + i * GT;
            int r = id >> 2, q = id & 3;
            cp16(bbase + r * ASTR_B + q * 16,
                 Bp + (size_t)r * K + k0 + q * 8);
        }
        cp_commit();
    };

    issue_stage(0);
    issue_stage(1);

    const uint32_t a_off = (uint32_t)(lane & 15) * ASTR_B + (uint32_t)(lane >> 4) * 16;
    const uint32_t b_off = (uint32_t)((lane & 7) + ((lane >> 4) << 3)) * ASTR_B
                         + (uint32_t)((lane >> 3) & 1) * 16;

    for (int c = 0; c < nchunk; c++) {
        cp_wait1();
        __syncthreads();
        if (c + 2 < nchunk) issue_stage(c + 2);
        else cp_commit();

        const uint32_t abase = sbase + (c % 3) * STAGE_BYTES;
        const uint32_t bbase = abase + A_BYTES;

#pragma unroll
        for (int s = 0; s < 2; s++) {
            const uint32_t kb = s * 32;
            uint32_t af[2][4];
#pragma unroll
            for (int mt = 0; mt < 2; mt++)
                ldm_x4(af[mt][0], af[mt][1], af[mt][2], af[mt][3],
                       abase + (wm * 32 + mt * 16) * ASTR_B + a_off + kb);
#pragma unroll
            for (int ntp = 0; ntp < 4; ntp++) {
                uint32_t b0, b1, b2, b3;
                ldm_x4(b0, b1, b2, b3,
                       bbase + (wn * 64 + ntp * 16) * ASTR_B + b_off + kb);
#pragma unroll
                for (int mt = 0; mt < 2; mt++) {
                    mma_f16(acc[mt][2 * ntp][0], acc[mt][2 * ntp][1],
                            acc[mt][2 * ntp][2], acc[mt][2 * ntp][3],
                            af[mt][0], af[mt][1], af[mt][2], af[mt][3], b0, b1);
                    mma_f16(acc[mt][2 * ntp + 1][0], acc[mt][2 * ntp + 1][1],
                            acc[mt][2 * ntp + 1][2], acc[mt][2 * ntp + 1][3],
                            af[mt][0], af[mt][1], af[mt][2], af[mt][3], b2, b3);
                }
            }
        }
    }

#pragma unroll
    for (int mt = 0; mt < 2; mt++) {
#pragma unroll
        for (int nt = 0; nt < 8; nt++) {
            int c = colBase + wn * 64 + nt * 8 + 2 * qid;
            float bx = bias[c], by = bias[c + 1];
            int r0 = rowBase + wm * 32 + mt * 16 + grp;
            if (HALF_OUT) {
                __half* C = (__half*)Cv;
                __half2 o0 = __floats2half2_rn(acc[mt][nt][0] + bx, acc[mt][nt][1] + by);
                *reinterpret_cast<__half2*>(C + (size_t)r0 * N + c) = o0;
                __half2 o1 = __floats2half2_rn(acc[mt][nt][2] + bx, acc[mt][nt][3] + by);
                *reinterpret_cast<__half2*>(C + (size_t)(r0 + 8) * N + c) = o1;
            } else {
                float* C = (float*)Cv;
                float2 o0 = make_float2(acc[mt][nt][0] + bx, acc[mt][nt][1] + by);
                *reinterpret_cast<float2*>(C + (size_t)r0 * N + c) = o0;
                float2 o1 = make_float2(acc[mt][nt][2] + bx, acc[mt][nt][3] + by);
                *reinterpret_cast<float2*>(C + (size_t)(r0 + 8) * N + c) = o1;
            }
        }
    }
}

// ---------------------------------------------------------------------------
// Fused flash attention, base-2 softmax + ones-column rowsum.
// smem halves: Ks[128][88] | Vs[80][136] (V^T; rows 64-79 = ones/zeros) |
//              Ps[128][136]
// ---------------------------------------------------------------------------
#define KS_W 44
#define VS_W 68
#define PS_W 68
#define KS_B 176
#define VS_B 272
#define PS_B 272
#define VS_ROWS 80
#define KS_OFFW 0
#define VS_OFFW (128 * KS_W)                     // 5632
#define PS_OFFW (VS_OFFW + VS_ROWS * VS_W)       // 11072
#define FA_SMEM_WORDS (PS_OFFW + 128 * PS_W)     // 19776
#define FA_SMEM_BYTES (FA_SMEM_WORDS * 4)        // 79104

// Q scale: 0.125 (1/sqrt(64)) * log2(e) -> scores in log2 domain
#define QSCALE 0.18033688f

__global__ __launch_bounds__(256, 2) void fa_kernel(
    const __half* __restrict__ qkv, __half* __restrict__ att)
{
    extern __shared__ uint32_t smw[];
    uint32_t* Ks = smw + KS_OFFW;
    uint32_t* Vs = smw + VS_OFFW;
    uint32_t* Ps = smw + PS_OFFW;
    __half*  Vsh = reinterpret_cast<__half*>(Vs);

    const int qb = 15 - blockIdx.x;
    const int bh = blockIdx.y;
    const int b = bh >> 4, h = bh & 15;
    const __half* Qp = qkv + (size_t)b * SEQ * QKVN + h * HDIM;
    const __half* Kp = Qp + DMODEL;
    const __half* Vp = Qp + 2 * DMODEL;

    const int tid = threadIdx.x, warp = tid >> 5, lane = tid & 31;
    const int grp = lane >> 2, qid = lane & 3;

    const uint32_t ks_base = smem_u32(smw) + KS_OFFW * 4;
    const uint32_t vs_base = smem_u32(smw) + VS_OFFW * 4;
    const uint32_t ps_base = smem_u32(smw) + PS_OFFW * 4;

    const uint32_t aK_off = (uint32_t)(warp * 16 + (lane & 15)) * KS_B
                          + (uint32_t)(lane >> 4) * 16;
    const uint32_t bK_off = (uint32_t)((lane & 7) + ((lane >> 4) << 3)) * KS_B
                          + (uint32_t)((lane >> 3) & 1) * 16;
    const uint32_t aP_off = (uint32_t)(warp * 16 + (lane & 15)) * PS_B
                          + (uint32_t)(lane >> 4) * 16;
    const uint32_t bV_off = (uint32_t)((lane & 7) + ((lane >> 4) << 3)) * VS_B
                          + (uint32_t)((lane >> 3) & 1) * 16;

    // ---- stage Q (scaled) into Ks rows; init ones/zeros rows of Vs ----
    {
        const __half2 sc = __floats2half2_rn(QSCALE, QSCALE);
#pragma unroll
        for (int i = 0; i < 4; i++) {
            int id = tid + i * 256;
            int r = id >> 3, u = id & 7;
            uint2 v = *reinterpret_cast<const uint2*>(
                Qp + (size_t)(qb * 128 + r) * QKVN + u * 8 + 0);
            uint2 w = *reinterpret_cast<const uint2*>(
                Qp + (size_t)(qb * 128 + r) * QKVN + u * 8 + 4);
            __half2 h0 = __hmul2(*(__half2*)&v.x, sc);
            __half2 h1 = __hmul2(*(__half2*)&v.y, sc);
            __half2 h2 = __hmul2(*(__half2*)&w.x, sc);
            __half2 h3 = __hmul2(*(__half2*)&w.y, sc);
            uint32_t* dst = Ks + r * KS_W + u * 4;
            dst[0] = *(uint32_t*)&h0; dst[1] = *(uint32_t*)&h1;
            dst[2] = *(uint32_t*)&h2; dst[3] = *(uint32_t*)&h3;
        }
        // Vs rows 64..79: row 64 = 1.0 (rowsum column), rows 65..79 = 0
#pragma unroll
        for (int i = 0; i < 4; i++) {
            int id = tid + i * 256;            // 0..1023
            int r = 64 + (id >> 6);            // 64..79
            int c = id & 63;                   // word 0..63 (halves 0..127)
            Vs[r * VS_W + c] = (r == 64) ? 0x3C003C00u : 0u;
        }
    }
    __syncthreads();

    uint32_t aq[4][4];
#pragma unroll
    for (int s = 0; s < 4; s++)
        ldm_x4(aq[s][0], aq[s][1], aq[s][2], aq[s][3], ks_base + aK_off + s * 32);

    float m0v = -CUDART_INF_F, m1v = -CUDART_INF_F;
    float acc_o[8][4];
    float acc_l[4];
#pragma unroll
    for (int j = 0; j < 8; j++)
#pragma unroll
        for (int v = 0; v < 4; v++) acc_o[j][v] = 0.f;
#pragma unroll
    for (int v = 0; v < 4; v++) acc_l[v] = 0.f;

    for (int kb = 0; kb <= qb; kb++) {
        __syncthreads();
#pragma unroll
        for (int i = 0; i < 4; i++) {
            int id = tid + i * 256;
            int r = id >> 3, u = id & 7;
            uint4 v = *reinterpret_cast<const uint4*>(
                Kp + (size_t)(kb * 128 + r) * QKVN + u * 8);
            uint32_t* dst = Ks + r * KS_W + u * 4;
            dst[0] = v.x; dst[1] = v.y; dst[2] = v.z; dst[3] = v.w;
        }
#pragma unroll
        for (int i = 0; i < 8; i++) {
            int id = tid + i * 256;
            int k = id >> 4, dg = id & 15;
            uint2 v = *reinterpret_cast<const uint2*>(
                Vp + (size_t)(kb * 128 + k) * QKVN + dg * 4);
            __half2 p0 = *(__half2*)&v.x;
            __half2 p1 = *(__half2*)&v.y;
            Vsh[(dg * 4 + 0) * (VS_W * 2) + k] = __low2half(p0);
            Vsh[(dg * 4 + 1) * (VS_W * 2) + k] = __high2half(p0);
            Vsh[(dg * 4 + 2) * (VS_W * 2) + k] = __low2half(p1);
            Vsh[(dg * 4 + 3) * (VS_W * 2) + k] = __high2half(p1);
        }
        __syncthreads();

        // ---- S = Q K^T (log2-scaled) ----
        float s_[16][4];
#pragma unroll
        for (int nt = 0; nt < 16; nt++)
#pragma unroll
            for (int v = 0; v < 4; v++) s_[nt][v] = 0.f;
#pragma unroll
        for (int s = 0; s < 4; s++) {
#pragma unroll
            for (int ntp = 0; ntp < 8; ntp++) {
                uint32_t b0, b1, b2, b3;
                ldm_x4(b0, b1, b2, b3, ks_base + ntp * 16 * KS_B + bK_off + s * 32);
                mma_f16(s_[2 * ntp][0], s_[2 * ntp][1], s_[2 * ntp][2], s_[2 * ntp][3],
                        aq[s][0], aq[s][1], aq[s][2], aq[s][3], b0, b1);
                mma_f16(s_[2 * ntp + 1][0], s_[2 * ntp + 1][1],
                        s_[2 * ntp + 1][2], s_[2 * ntp + 1][3],
                        aq[s][0], aq[s][1], aq[s][2], aq[s][3], b2, b3);
            }
        }

        if (kb == qb) {
            const int r0 = warp * 16 + grp, r1 = r0 + 8;
#pragma unroll
            for (int nt = 0; nt < 16; nt++) {
                int c = nt * 8 + 2 * qid;
                if (c > r0)     s_[nt][0] = -CUDART_INF_F;
                if (c + 1 > r0) s_[nt][1] = -CUDART_INF_F;
                if (c > r1)     s_[nt][2] = -CUDART_INF_F;
                if (c + 1 > r1) s_[nt][3] = -CUDART_INF_F;
            }
        }

        // ---- online softmax (base 2) ----
        float mx0 = -CUDART_INF_F, mx1 = -CUDART_INF_F;
#pragma unroll
        for (int nt = 0; nt < 16; nt++) {
            mx0 = fmaxf(mx0, fmaxf(s_[nt][0], s_[nt][1]));
            mx1 = fmaxf(mx1, fmaxf(s_[nt][2], s_[nt][3]));
        }
        mx0 = fmaxf(mx0, __shfl_xor_sync(0xffffffffu, mx0, 1));
        mx0 = fmaxf(mx0, __shfl_xor_sync(0xffffffffu, mx0, 2));
        mx1 = fmaxf(mx1, __shfl_xor_sync(0xffffffffu, mx1, 1));
        mx1 = fmaxf(mx1, __shfl_xor_sync(0xffffffffu, mx1, 2));

        float mn0 = fmaxf(m0v, mx0), mn1 = fmaxf(m1v, mx1);
        float a0 = exp2f(m0v - mn0), a1 = exp2f(m1v - mn1);
        m0v = mn0; m1v = mn1;

        const int pr0 = (warp * 16 + grp) * PS_W;
        const int pr1 = pr0 + 8 * PS_W;
#pragma unroll
        for (int nt = 0; nt < 16; nt++) {
            __half2 d0 = __floats2half2_rn(s_[nt][0] - mn0, s_[nt][1] - mn0);
            __half2 d1 = __floats2half2_rn(s_[nt][2] - mn1, s_[nt][3] - mn1);
            Ps[pr0 + nt * 4 + qid] = h2exp2(*(uint32_t*)&d0);
            Ps[pr1 + nt * 4 + qid] = h2exp2(*(uint32_t*)&d1);
        }

#pragma unroll
        for (int nt = 0; nt < 8; nt++) {
            acc_o[nt][0] *= a0; acc_o[nt][1] *= a0;
            acc_o[nt][2] *= a1; acc_o[nt][3] *= a1;
        }
        acc_l[0] *= a0; acc_l[1] *= a0;
        acc_l[2] *= a1; acc_l[3] *= a1;

        // ---- O += P V; l += P 1 (via ones column) ----
#pragma unroll
        for (int s = 0; s < 8; s++) {
            uint32_t ap0, ap1, ap2, ap3;
            ldm_x4(ap0, ap1, ap2, ap3, ps_base + aP_off + s * 32);
#pragma unroll
            for (int ntp = 0; ntp < 4; ntp++) {
                uint32_t b0, b1, b2, b3;
                ldm_x4(b0, b1, b2, b3, vs_base + ntp * 16 * VS_B + bV_off + s * 32);
                mma_f16(acc_o[2 * ntp][0], acc_o[2 * ntp][1],
                        acc_o[2 * ntp][2], acc_o[2 * ntp][3],
                        ap0, ap1, ap2, ap3, b0, b1);
                mma_f16(acc_o[2 * ntp + 1][0], acc_o[2 * ntp + 1][1],
                        acc_o[2 * ntp + 1][2], acc_o[2 * ntp + 1][3],
                        ap0, ap1, ap2, ap3, b2, b3);
            }
            {
                uint32_t e0, e1, e2, e3;
                ldm_x4(e0, e1, e2, e3, vs_base + 64 * VS_B + bV_off + s * 32);
                mma_f16(acc_l[0], acc_l[1], acc_l[2], acc_l[3],
                        ap0, ap1, ap2, ap3, e0, e1);
            }
        }
    }

    // ---- epilogue: l lives in col 64 (qid==0 lanes) ----
    float lr0 = __shfl_sync(0xffffffffu, acc_l[0], lane & 28);
    float lr1 = __shfl_sync(0xffffffffu, acc_l[2], lane & 28);
    const float inv0 = 1.f / lr0, inv1 = 1.f / lr1;
    const int r0 = qb * 128 + warp * 16 + grp;
#pragma unroll
    for (int nt = 0; nt < 8; nt++) {
        int col = h * HDIM + nt * 8 + 2 * qid;
        __half2 o0 = __floats2half2_rn(acc_o[nt][0] * inv0, acc_o[nt][1] * inv0);
        *reinterpret_cast<__half2*>(att + (size_t)(b * SEQ + r0) * DMODEL + col) = o0;
        __half2 o1 = __floats2half2_rn(acc_o[nt][2] * inv1, acc_o[nt][3] * inv1);
        *reinterpret_cast<__half2*>(att + (size_t)(b * SEQ + r0 + 8) * DMODEL + col) = o1;
    }
}

// ---------------------------------------------------------------------------
extern "C" void kernel_launch(void* const* d_in, const int* in_sizes, int n_in,
                              void* d_out, int out_size)
{
    const float* x    = (const float*)d_in[0];
    const float* Wqkv = (const float*)d_in[1];
    const float* bqkv = (const float*)d_in[2];
    const float* Wp   = (const float*)d_in[3];
    const float* bp   = (const float*)d_in[4];
    float* out = (float*)d_out;

    __half *qkv, *att, *xh, *wqkv_t, *wp_t;
    cudaGetSymbolAddress((void**)&qkv, g_qkv);
    cudaGetSymbolAddress((void**)&att, g_att);
    cudaGetSymbolAddress((void**)&xh, g_xh);
    cudaGetSymbolAddress((void**)&wqkv_t, g_wqkv_t);
    cudaGetSymbolAddress((void**)&wp_t, g_wp_t);

    cudaFuncSetAttribute(fa_kernel,
                         cudaFuncAttributeMaxDynamicSharedMemorySize, FA_SMEM_BYTES);
    cudaFuncSetAttribute(gemm_f16_kernel<1>,
                         cudaFuncAttributeMaxDynamicSharedMemorySize, GEMM_SMEM_BYTES);
    cudaFuncSetAttribute(gemm_f16_kernel<0>,
                         cudaFuncAttributeMaxDynamicSharedMemorySize, GEMM_SMEM_BYTES);

    x2h_kernel<<<(MROWS * DMODEL / 4 + 255) / 256, 256>>>(x, xh);
    {
        dim3 blk(32, 8);
        transpose_h_kernel<<<dim3(DMODEL / 32, QKVN / 32), blk>>>(Wqkv, wqkv_t, DMODEL, QKVN);
        transpose_h_kernel<<<dim3(DMODEL / 32, DMODEL / 32), blk>>>(Wp, wp_t, DMODEL, DMODEL);
    }
    {
        dim3 grid(QKVN / GN, MROWS / GM);
        gemm_f16_kernel<1><<<grid, GT, GEMM_SMEM_BYTES>>>(xh, wqkv_t, bqkv, qkv,
                                                          MROWS, QKVN, DMODEL);
    }
    {
        dim3 grid(SEQ / 128, BH);
        fa_kernel<<<grid, 256, FA_SMEM_BYTES>>>(qkv, att);
    }
    {
        dim3 grid(DMODEL / GN, MROWS / GM);
        gemm_f16_kernel<0><<<grid, GT, GEMM_SMEM_BYTES>>>(att, wp_t, bp, out,
                                                          MROWS, DMODEL, DMODEL);
    }
}

// round 10
// speedup vs baseline: 6.9207x; 1.1484x over previous
#include <cuda_runtime.h>
#include <cuda_fp16.h>
#include <math_constants.h>
#include <cstdint>

#define Bsz 4
#define SEQ 2048
#define DMODEL 1024
#define NHEAD 16
#define HDIM 64
#define BH (Bsz * NHEAD)          // 64
#define MROWS (Bsz * SEQ)         // 8192
#define QKVN (3 * DMODEL)         // 3072

__device__ __half g_qkv[MROWS * QKVN];
__device__ __half g_att[MROWS * DMODEL];
__device__ __half g_xh[MROWS * DMODEL];
__device__ __half g_wqkv_t[QKVN * DMODEL];
__device__ __half g_wp_t[DMODEL * DMODEL];

// ---------------------------------------------------------------------------
__device__ __forceinline__ void mma_f16(
    float& d0, float& d1, float& d2, float& d3,
    uint32_t a0, uint32_t a1, uint32_t a2, uint32_t a3,
    uint32_t b0, uint32_t b1)
{
    asm volatile(
        "mma.sync.aligned.m16n8k16.row.col.f32.f16.f16.f32 "
        "{%0,%1,%2,%3}, {%4,%5,%6,%7}, {%8,%9}, {%0,%1,%2,%3};\n"
        : "+f"(d0), "+f"(d1), "+f"(d2), "+f"(d3)
        : "r"(a0), "r"(a1), "r"(a2), "r"(a3), "r"(b0), "r"(b1));
}

__device__ __forceinline__ void ldm_x4(
    uint32_t& r0, uint32_t& r1, uint32_t& r2, uint32_t& r3, uint32_t addr)
{
    asm volatile("ldmatrix.sync.aligned.m8n8.x4.shared.b16 {%0,%1,%2,%3}, [%4];"
        : "=r"(r0), "=r"(r1), "=r"(r2), "=r"(r3) : "r"(addr));
}

__device__ __forceinline__ void ldm_x4t(
    uint32_t& r0, uint32_t& r1, uint32_t& r2, uint32_t& r3, uint32_t addr)
{
    asm volatile("ldmatrix.sync.aligned.m8n8.x4.trans.shared.b16 {%0,%1,%2,%3}, [%4];"
        : "=r"(r0), "=r"(r1), "=r"(r2), "=r"(r3) : "r"(addr));
}

__device__ __forceinline__ uint32_t h2exp2(uint32_t x) {
    uint32_t r;
    asm("ex2.approx.f16x2 %0, %1;" : "=r"(r) : "r"(x));
    return r;
}

__device__ __forceinline__ void cp16(uint32_t dst, const void* src) {
    asm volatile("cp.async.cg.shared.global [%0], [%1], 16;"
                 :: "r"(dst), "l"(src) : "memory");
}
__device__ __forceinline__ void cp_commit() {
    asm volatile("cp.async.commit_group;" ::: "memory");
}
__device__ __forceinline__ void cp_wait1() {
    asm volatile("cp.async.wait_group 1;" ::: "memory");
}
__device__ __forceinline__ void cp_wait0() {
    asm volatile("cp.async.wait_group 0;" ::: "memory");
}
__device__ __forceinline__ uint32_t smem_u32(const void* p) {
    uint32_t a;
    asm("{ .reg .u64 t; cvta.to.shared.u64 t, %1; cvt.u32.u64 %0, t; }"
        : "=r"(a) : "l"(p));
    return a;
}

// ---------------------------------------------------------------------------
// prepass
// ---------------------------------------------------------------------------
__global__ __launch_bounds__(256) void x2h_kernel(
    const float* __restrict__ x, __half* __restrict__ xh)
{
    size_t i = ((size_t)blockIdx.x * 256 + threadIdx.x) * 4;
    if (i < (size_t)MROWS * DMODEL) {
        float4 v = *reinterpret_cast<const float4*>(x + i);
        __half2 h0 = __floats2half2_rn(v.x, v.y);
        __half2 h1 = __floats2half2_rn(v.z, v.w);
        *reinterpret_cast<uint2*>(xh + i) =
            make_uint2(*(uint32_t*)&h0, *(uint32_t*)&h1);
    }
}

__global__ __launch_bounds__(256) void transpose_h_kernel(
    const float* __restrict__ W, __half* __restrict__ Wt, int K, int N)
{
    __shared__ float t[32][33];
    const int kb = blockIdx.x * 32, nb = blockIdx.y * 32;
    const int tx = threadIdx.x, ty = threadIdx.y;
#pragma unroll
    for (int i = 0; i < 32; i += 8)
        t[ty + i][tx] = W[(size_t)(kb + ty + i) * N + nb + tx];
    __syncthreads();
#pragma unroll
    for (int i = 0; i < 32; i += 8)
        Wt[(size_t)(nb + ty + i) * K + kb + tx] = __float2half_rn(t[tx][ty + i]);
}

// ---------------------------------------------------------------------------
// fp16 GEMM (unchanged from R8/R9)
// ---------------------------------------------------------------------------
#define GM 128
#define GN 256
#define GKH 32
#define ASTR_B 80
#define A_BYTES (GM * ASTR_B)
#define B_BYTES (GN * ASTR_B)
#define STAGE_BYTES (A_BYTES + B_BYTES)
#define GEMM_SMEM_BYTES (3 * STAGE_BYTES)   // 92160
#define GT 512

template <int HALF_OUT>
__global__ __launch_bounds__(GT, 1) void gemm_f16_kernel(
    const __half* __restrict__ A, const __half* __restrict__ Bt,
    const float* __restrict__ bias, void* __restrict__ Cv,
    int M, int N, int K)
{
    extern __shared__ uint32_t smw[];
    const int tid  = threadIdx.x;
    const int warp = tid >> 5;
    const int lane = tid & 31;
    const int grp  = lane >> 2;
    const int qid  = lane & 3;
    const int wm   = warp & 3;
    const int wn   = warp >> 2;
    const int rowBase = blockIdx.y * GM;
    const int colBase = blockIdx.x * GN;

    const __half* Ap = A + (size_t)rowBase * K;
    const __half* Bp = Bt + (size_t)colBase * K;
    const uint32_t sbase = smem_u32(smw);

    float acc[2][8][4];
#pragma unroll
    for (int mt = 0; mt < 2; mt++)
#pragma unroll
        for (int nt = 0; nt < 8; nt++)
#pragma unroll
            for (int v = 0; v < 4; v++) acc[mt][nt][v] = 0.f;

    const int nchunk = K / GKH;

    auto issue_stage = [&](int c) {
        const uint32_t abase = sbase + (c % 3) * STAGE_BYTES;
        const uint32_t bbase = abase + A_BYTES;
        const int k0 = c * GKH;
        {
            int r = tid >> 2, q = tid & 3;
            cp16(abase + r * ASTR_B + q * 16,
                 Ap + (size_t)r * K + k0 + q * 8);
        }
#pragma unroll
        for (int i = 0; i < 2; i++) {
            int id = tid + i * GT;
            int r = id >> 2, q = id & 3;
            cp16(bbase + r * ASTR_B + q * 16,
                 Bp + (size_t)r * K + k0 + q * 8);
        }
        cp_commit();
    };

    issue_stage(0);
    issue_stage(1);

    const uint32_t a_off = (uint32_t)(lane & 15) * ASTR_B + (uint32_t)(lane >> 4) * 16;
    const uint32_t b_off = (uint32_t)((lane & 7) + ((lane >> 4) << 3)) * ASTR_B
                         + (uint32_t)((lane >> 3) & 1) * 16;

    for (int c = 0; c < nchunk; c++) {
        cp_wait1();
        __syncthreads();
        if (c + 2 < nchunk) issue_stage(c + 2);
        else cp_commit();

        const uint32_t abase = sbase + (c % 3) * STAGE_BYTES;
        const uint32_t bbase = abase + A_BYTES;

#pragma unroll
        for (int s = 0; s < 2; s++) {
            const uint32_t kb = s * 32;
            uint32_t af[2][4];
#pragma unroll
            for (int mt = 0; mt < 2; mt++)
                ldm_x4(af[mt][0], af[mt][1], af[mt][2], af[mt][3],
                       abase + (wm * 32 + mt * 16) * ASTR_B + a_off + kb);
#pragma unroll
            for (int ntp = 0; ntp < 4; ntp++) {
                uint32_t b0, b1, b2, b3;
                ldm_x4(b0, b1, b2, b3,
                       bbase + (wn * 64 + ntp * 16) * ASTR_B + b_off + kb);
#pragma unroll
                for (int mt = 0; mt < 2; mt++) {
                    mma_f16(acc[mt][2 * ntp][0], acc[mt][2 * ntp][1],
                            acc[mt][2 * ntp][2], acc[mt][2 * ntp][3],
                            af[mt][0], af[mt][1], af[mt][2], af[mt][3], b0, b1);
                    mma_f16(acc[mt][2 * ntp + 1][0], acc[mt][2 * ntp + 1][1],
                            acc[mt][2 * ntp + 1][2], acc[mt][2 * ntp + 1][3],
                            af[mt][0], af[mt][1], af[mt][2], af[mt][3], b2, b3);
                }
            }
        }
    }

#pragma unroll
    for (int mt = 0; mt < 2; mt++) {
#pragma unroll
        for (int nt = 0; nt < 8; nt++) {
            int c = colBase + wn * 64 + nt * 8 + 2 * qid;
            float bx = bias[c], by = bias[c + 1];
            int r0 = rowBase + wm * 32 + mt * 16 + grp;
            if (HALF_OUT) {
                __half* C = (__half*)Cv;
                __half2 o0 = __floats2half2_rn(acc[mt][nt][0] + bx, acc[mt][nt][1] + by);
                *reinterpret_cast<__half2*>(C + (size_t)r0 * N + c) = o0;
                __half2 o1 = __floats2half2_rn(acc[mt][nt][2] + bx, acc[mt][nt][3] + by);
                *reinterpret_cast<__half2*>(C + (size_t)(r0 + 8) * N + c) = o1;
            } else {
                float* C = (float*)Cv;
                float2 o0 = make_float2(acc[mt][nt][0] + bx, acc[mt][nt][1] + by);
                *reinterpret_cast<float2*>(C + (size_t)r0 * N + c) = o0;
                float2 o1 = make_float2(acc[mt][nt][2] + bx, acc[mt][nt][3] + by);
                *reinterpret_cast<float2*>(C + (size_t)(r0 + 8) * N + c) = o1;
            }
        }
    }
}

// ---------------------------------------------------------------------------
// Fused flash attention: cp.async double-buffered K/V, ldmatrix.trans V,
// base-2 softmax, ones-column rowsum.
// smem: Ks[2][128][88h] | Vs[2][128][88h] (row-major, col64=1) | Ps[128][136h]
// ---------------------------------------------------------------------------
#define KS_B 176                      // bytes per K/V smem row
#define KSB_SIZE (128 * KS_B)         // 22528
#define PS_B 272
#define PS_W 68
#define KS0_OFF 0
#define KS1_OFF KSB_SIZE
#define VS0_OFF (2 * KSB_SIZE)
#define VS1_OFF (3 * KSB_SIZE)
#define PS_OFF  (4 * KSB_SIZE)        // 90112
#define FA_SMEM_BYTES (PS_OFF + 128 * PS_B)   // 124928

#define QSCALE 0.18033688f            // 0.125 * log2(e)

__global__ __launch_bounds__(256, 1) void fa_kernel(
    const __half* __restrict__ qkv, __half* __restrict__ att)
{
    extern __shared__ uint32_t smw[];
    const uint32_t sbase = smem_u32(smw);
    const uint32_t ps_base = sbase + PS_OFF;
    uint32_t* Ps = smw + PS_OFF / 4;

    const int qb = 15 - blockIdx.x;
    const int bh = blockIdx.y;
    const int b = bh >> 4, h = bh & 15;
    const __half* Qp = qkv + (size_t)b * SEQ * QKVN + h * HDIM;
    const __half* Kp = Qp + DMODEL;
    const __half* Vp = Qp + 2 * DMODEL;

    const int tid = threadIdx.x, warp = tid >> 5, lane = tid & 31;
    const int grp = lane >> 2, qid = lane & 3;

    // ldmatrix lane offsets
    const uint32_t aQ_off = (uint32_t)(warp * 16 + (lane & 15)) * PS_B
                          + (uint32_t)(lane >> 4) * 16;
    const uint32_t bK_off = (uint32_t)((lane & 7) + ((lane >> 4) << 3)) * KS_B
                          + (uint32_t)((lane >> 3) & 1) * 16;
    const uint32_t aP_off = aQ_off;
    // V trans fragments: rows = k, col-chunks = n
    const uint32_t bVt_off = (uint32_t)((lane & 7) + (((lane >> 3) & 1) << 3)) * KS_B
                           + (uint32_t)(lane >> 4) * 16;

    // cp.async staging of one K/V block (1024+1024 chunks, 8 per thread)
    auto issue_kv = [&](int kb) {
        const uint32_t kbuf = sbase + ((kb & 1) ? KS1_OFF : KS0_OFF);
        const uint32_t vbuf = sbase + ((kb & 1) ? VS1_OFF : VS0_OFF);
#pragma unroll
        for (int i = 0; i < 4; i++) {
            int id = tid + i * 256;
            int r = id >> 3, q = id & 7;
            cp16(kbuf + r * KS_B + q * 16,
                 Kp + (size_t)(kb * 128 + r) * QKVN + q * 8);
            cp16(vbuf + r * KS_B + q * 16,
                 Vp + (size_t)(kb * 128 + r) * QKVN + q * 8);
        }
        cp_commit();
    };

    issue_kv(0);

    // ---- stage Q (scaled) into Ps; init ones/zero cols of both V buffers ----
    {
        const __half2 sc = __floats2half2_rn(QSCALE, QSCALE);
#pragma unroll
        for (int i = 0; i < 4; i++) {
            int id = tid + i * 256;
            int r = id >> 3, u = id & 7;
            uint2 v = *reinterpret_cast<const uint2*>(
                Qp + (size_t)(qb * 128 + r) * QKVN + u * 8 + 0);
            uint2 w = *reinterpret_cast<const uint2*>(
                Qp + (size_t)(qb * 128 + r) * QKVN + u * 8 + 4);
            __half2 h0 = __hmul2(*(__half2*)&v.x, sc);
            __half2 h1 = __hmul2(*(__half2*)&v.y, sc);
            __half2 h2 = __hmul2(*(__half2*)&w.x, sc);
            __half2 h3 = __hmul2(*(__half2*)&w.y, sc);
            uint32_t* dst = Ps + r * PS_W + u * 4;
            dst[0] = *(uint32_t*)&h0; dst[1] = *(uint32_t*)&h1;
            dst[2] = *(uint32_t*)&h2; dst[3] = *(uint32_t*)&h3;
        }
        // V cols 64..87 (words 32..43 of each 176B row): col64=1.0, rest 0
        uint32_t* V0 = smw + VS0_OFF / 4;
        uint32_t* V1 = smw + VS1_OFF / 4;
#pragma unroll
        for (int i = 0; i < 6; i++) {
            int id = tid + i * 256;      // 0..1535
            int r = id / 12, w = id % 12;
            uint32_t val = (w == 0) ? 0x00003C00u : 0u;  // half[64]=1.0, half[65]=0
            V0[r * 44 + 32 + w] = val;
            V1[r * 44 + 32 + w] = val;
        }
    }
    __syncthreads();

    uint32_t aq[4][4];
#pragma unroll
    for (int s = 0; s < 4; s++)
        ldm_x4(aq[s][0], aq[s][1], aq[s][2], aq[s][3], ps_base + aQ_off + s * 32);

    float m0v = -CUDART_INF_F, m1v = -CUDART_INF_F;
    float acc_o[8][4];
    float acc_l[4];
#pragma unroll
    for (int j = 0; j < 8; j++)
#pragma unroll
        for (int v = 0; v < 4; v++) acc_o[j][v] = 0.f;
#pragma unroll
    for (int v = 0; v < 4; v++) acc_l[v] = 0.f;

    for (int kb = 0; kb <= qb; kb++) {
        cp_wait0();
        __syncthreads();
        if (kb < qb) issue_kv(kb + 1);

        const uint32_t kbuf = sbase + ((kb & 1) ? KS1_OFF : KS0_OFF);
        const uint32_t vbuf = sbase + ((kb & 1) ? VS1_OFF : VS0_OFF);

        // ---- S = Q K^T (log2-scaled) ----
        float s_[16][4];
#pragma unroll
        for (int nt = 0; nt < 16; nt++)
#pragma unroll
            for (int v = 0; v < 4; v++) s_[nt][v] = 0.f;
#pragma unroll
        for (int s = 0; s < 4; s++) {
#pragma unroll
            for (int ntp = 0; ntp < 8; ntp++) {
                uint32_t b0, b1, b2, b3;
                ldm_x4(b0, b1, b2, b3, kbuf + ntp * 16 * KS_B + bK_off + s * 32);
                mma_f16(s_[2 * ntp][0], s_[2 * ntp][1], s_[2 * ntp][2], s_[2 * ntp][3],
                        aq[s][0], aq[s][1], aq[s][2], aq[s][3], b0, b1);
                mma_f16(s_[2 * ntp + 1][0], s_[2 * ntp + 1][1],
                        s_[2 * ntp + 1][2], s_[2 * ntp + 1][3],
                        aq[s][0], aq[s][1], aq[s][2], aq[s][3], b2, b3);
            }
        }

        if (kb == qb) {
            const int r0 = warp * 16 + grp, r1 = r0 + 8;
#pragma unroll
            for (int nt = 0; nt < 16; nt++) {
                int c = nt * 8 + 2 * qid;
                if (c > r0)     s_[nt][0] = -CUDART_INF_F;
                if (c + 1 > r0) s_[nt][1] = -CUDART_INF_F;
                if (c > r1)     s_[nt][2] = -CUDART_INF_F;
                if (c + 1 > r1) s_[nt][3] = -CUDART_INF_F;
            }
        }

        // ---- online softmax (base 2) ----
        float mx0 = -CUDART_INF_F, mx1 = -CUDART_INF_F;
#pragma unroll
        for (int nt = 0; nt < 16; nt++) {
            mx0 = fmaxf(mx0, fmaxf(s_[nt][0], s_[nt][1]));
            mx1 = fmaxf(mx1, fmaxf(s_[nt][2], s_[nt][3]));
        }
        mx0 = fmaxf(mx0, __shfl_xor_sync(0xffffffffu, mx0, 1));
        mx0 = fmaxf(mx0, __shfl_xor_sync(0xffffffffu, mx0, 2));
        mx1 = fmaxf(mx1, __shfl_xor_sync(0xffffffffu, mx1, 1));
        mx1 = fmaxf(mx1, __shfl_xor_sync(0xffffffffu, mx1, 2));

        float mn0 = fmaxf(m0v, mx0), mn1 = fmaxf(m1v, mx1);
        float a0 = exp2f(m0v - mn0), a1 = exp2f(m1v - mn1);
        m0v = mn0; m1v = mn1;

        const int pr0 = (warp * 16 + grp) * PS_W;
        const int pr1 = pr0 + 8 * PS_W;
#pragma unroll
        for (int nt = 0; nt < 16; nt++) {
            __half2 d0 = __floats2half2_rn(s_[nt][0] - mn0, s_[nt][1] - mn0);
            __half2 d1 = __floats2half2_rn(s_[nt][2] - mn1, s_[nt][3] - mn1);
            Ps[pr0 + nt * 4 + qid] = h2exp2(*(uint32_t*)&d0);
            Ps[pr1 + nt * 4 + qid] = h2exp2(*(uint32_t*)&d1);
        }

#pragma unroll
        for (int nt = 0; nt < 8; nt++) {
            acc_o[nt][0] *= a0; acc_o[nt][1] *= a0;
            acc_o[nt][2] *= a1; acc_o[nt][3] *= a1;
        }
        acc_l[0] *= a0; acc_l[1] *= a0;
        acc_l[2] *= a1; acc_l[3] *= a1;

        // ---- O += P V; l += P 1 (V row-major, trans ldmatrix) ----
#pragma unroll
        for (int s = 0; s < 8; s++) {
            uint32_t ap0, ap1, ap2, ap3;
            ldm_x4(ap0, ap1, ap2, ap3, ps_base + aP_off + s * 32);
            const uint32_t vrow = vbuf + s * 16 * KS_B + bVt_off;
#pragma unroll
            for (int ntp = 0; ntp < 4; ntp++) {
                uint32_t b0, b1, b2, b3;
                ldm_x4t(b0, b1, b2, b3, vrow + ntp * 32);
                mma_f16(acc_o[2 * ntp][0], acc_o[2 * ntp][1],
                        acc_o[2 * ntp][2], acc_o[2 * ntp][3],
                        ap0, ap1, ap2, ap3, b0, b1);
                mma_f16(acc_o[2 * ntp + 1][0], acc_o[2 * ntp + 1][1],
                        acc_o[2 * ntp + 1][2], acc_o[2 * ntp + 1][3],
                        ap0, ap1, ap2, ap3, b2, b3);
            }
            {
                uint32_t e0, e1, e2, e3;
                ldm_x4t(e0, e1, e2, e3, vrow + 128);
                mma_f16(acc_l[0], acc_l[1], acc_l[2], acc_l[3],
                        ap0, ap1, ap2, ap3, e0, e1);
            }
        }
        __syncthreads();   // Ps reads done before next iteration overwrites
    }

    // ---- epilogue: l in col 64 (qid==0 lanes) ----
    float lr0 = __shfl_sync(0xffffffffu, acc_l[0], lane & 28);
    float lr1 = __shfl_sync(0xffffffffu, acc_l[2], lane & 28);
    const float inv0 = 1.f / lr0, inv1 = 1.f / lr1;
    const int r0 = qb * 128 + warp * 16 + grp;
#pragma unroll
    for (int nt = 0; nt < 8; nt++) {
        int col = h * HDIM + nt * 8 + 2 * qid;
        __half2 o0 = __floats2half2_rn(acc_o[nt][0] * inv0, acc_o[nt][1] * inv0);
        *reinterpret_cast<__half2*>(att + (size_t)(b * SEQ + r0) * DMODEL + col) = o0;
        __half2 o1 = __floats2half2_rn(acc_o[nt][2] * inv1, acc_o[nt][3] * inv1);
        *reinterpret_cast<__half2*>(att + (size_t)(b * SEQ + r0 + 8) * DMODEL + col) = o1;
    }
}

// ---------------------------------------------------------------------------
extern "C" void kernel_launch(void* const* d_in, const int* in_sizes, int n_in,
                              void* d_out, int out_size)
{
    const float* x    = (const float*)d_in[0];
    const float* Wqkv = (const float*)d_in[1];
    const float* bqkv = (const float*)d_in[2];
    const float* Wp   = (const float*)d_in[3];
    const float* bp   = (const float*)d_in[4];
    float* out = (float*)d_out;

    __half *qkv, *att, *xh, *wqkv_t, *wp_t;
    cudaGetSymbolAddress((void**)&qkv, g_qkv);
    cudaGetSymbolAddress((void**)&att, g_att);
    cudaGetSymbolAddress((void**)&xh, g_xh);
    cudaGetSymbolAddress((void**)&wqkv_t, g_wqkv_t);
    cudaGetSymbolAddress((void**)&wp_t, g_wp_t);

    cudaFuncSetAttribute(fa_kernel,
                         cudaFuncAttributeMaxDynamicSharedMemorySize, FA_SMEM_BYTES);
    cudaFuncSetAttribute(gemm_f16_kernel<1>,
                         cudaFuncAttributeMaxDynamicSharedMemorySize, GEMM_SMEM_BYTES);
    cudaFuncSetAttribute(gemm_f16_kernel<0>,
                         cudaFuncAttributeMaxDynamicSharedMemorySize, GEMM_SMEM_BYTES);

    x2h_kernel<<<(MROWS * DMODEL / 4 + 255) / 256, 256>>>(x, xh);
    {
        dim3 blk(32, 8);
        transpose_h_kernel<<<dim3(DMODEL / 32, QKVN / 32), blk>>>(Wqkv, wqkv_t, DMODEL, QKVN);
        transpose_h_kernel<<<dim3(DMODEL / 32, DMODEL / 32), blk>>>(Wp, wp_t, DMODEL, DMODEL);
    }
    {
        dim3 grid(QKVN / GN, MROWS / GM);
        gemm_f16_kernel<1><<<grid, GT, GEMM_SMEM_BYTES>>>(xh, wqkv_t, bqkv, qkv,
                                                          MROWS, QKVN, DMODEL);
    }
    {
        dim3 grid(SEQ / 128, BH);
        fa_kernel<<<grid, 256, FA_SMEM_BYTES>>>(qkv, att);
    }
    {
        dim3 grid(DMODEL / GN, MROWS / GM);
        gemm_f16_kernel<0><<<grid, GT, GEMM_SMEM_BYTES>>>(att, wp_t, bp, out,
                                                          MROWS, DMODEL, DMODEL);
    }
}